// round 1
// baseline (speedup 1.0000x reference)
#include <cuda_runtime.h>
#include <cuda_bf16.h>
#include <math.h>

// Problem constants
#define B 64
#define S 512
#define E 768
#define H 64
#define G 192   // 3H
#define T 16
#define P 32

// ---------------- scratch (static device globals; no allocation) ----------------
__device__ float g_xp_f[B * S * G];      // 25.2 MB
__device__ float g_xp_b[B * S * G];      // 25.2 MB
__device__ float g_lstm[B * S * 2 * H];  // 16.8 MB
__device__ float g_qkv[B * S * 3 * P];   // 12.6 MB
__device__ float g_av[B * S * P];        // 4.2 MB
__device__ float g_emis[B * S * T];      // 2.1 MB
__device__ float g_weff1[2 * H * T];     // 128x16
__device__ float g_weff2[P * T];         // 32x16
__device__ float g_beff[T];
__device__ float g_nll[B];

__device__ __forceinline__ float sigmoidf_(float x) { return 1.0f / (1.0f + __expf(-x)); }

// ---------------- K1: xp = bert @ Wih^T + bih  (M=32768, N=192, K=768) ----------------
__global__ void gemm_xp(const float* __restrict__ A, const float* __restrict__ W,
                        const float* __restrict__ bias, int dir) {
    float* out = dir ? g_xp_b : g_xp_f;
    __shared__ float As[16][68];
    __shared__ float Bs[16][68];
    const int tx = threadIdx.x & 15;   // n micro
    const int ty = threadIdx.x >> 4;   // m micro
    const int bm = blockIdx.x * 64;
    const int bn = blockIdx.y * 64;

    float acc[4][4];
#pragma unroll
    for (int i = 0; i < 4; i++)
#pragma unroll
        for (int j = 0; j < 4; j++) acc[i][j] = 0.0f;

    for (int k0 = 0; k0 < E; k0 += 16) {
        const int kk = threadIdx.x & 15;
        const int r = threadIdx.x >> 4;
#pragma unroll
        for (int it = 0; it < 4; it++) {
            As[kk][r + 16 * it] = A[(size_t)(bm + r + 16 * it) * E + k0 + kk];
            Bs[kk][r + 16 * it] = W[(size_t)(bn + r + 16 * it) * E + k0 + kk];
        }
        __syncthreads();
#pragma unroll
        for (int k = 0; k < 16; k++) {
            float a[4], bb[4];
#pragma unroll
            for (int i = 0; i < 4; i++) a[i] = As[k][ty * 4 + i];
#pragma unroll
            for (int j = 0; j < 4; j++) bb[j] = Bs[k][tx * 4 + j];
#pragma unroll
            for (int i = 0; i < 4; i++)
#pragma unroll
                for (int j = 0; j < 4; j++) acc[i][j] = fmaf(a[i], bb[j], acc[i][j]);
        }
        __syncthreads();
    }
#pragma unroll
    for (int i = 0; i < 4; i++)
#pragma unroll
        for (int j = 0; j < 4; j++)
            out[(size_t)(bm + ty * 4 + i) * G + bn + tx * 4 + j] = acc[i][j] + bias[bn + tx * 4 + j];
}

// ---------------- K2: qkv = input2 @ in_proj_w^T + in_proj_b ----------------
__global__ void qkv_kernel(const float* __restrict__ in2, const float* __restrict__ W,
                           const float* __restrict__ bias) {
    int idx = blockIdx.x * blockDim.x + threadIdx.x;  // over 32768*96
    if (idx >= B * S * 3 * P) return;
    int m = idx / (3 * P);
    int n = idx % (3 * P);
    const float* x = in2 + (size_t)m * P;
    const float* w = W + (size_t)n * P;
    float acc = bias[n];
#pragma unroll
    for (int k = 0; k < P; k++) acc = fmaf(x[k], w[k], acc);
    g_qkv[idx] = acc;
}

// ---------------- K3: folded weights ----------------
__global__ void weff_kernel(const float* __restrict__ Wdense, const float* __restrict__ opw,
                            const float* __restrict__ opb, const float* __restrict__ Wfuse) {
    int tid = threadIdx.x;
    for (int i = tid; i < 2 * H * T; i += blockDim.x) {
        int j = i >> 4, t = i & 15;
        float s = 0.f;
#pragma unroll
        for (int u = 0; u < T; u++) s = fmaf(Wdense[j * T + u], Wfuse[u * T + t], s);
        g_weff1[i] = s;
    }
    for (int i = tid; i < P * T; i += blockDim.x) {
        int d = i >> 4, t = i & 15;
        float s = 0.f;
#pragma unroll
        for (int p = 0; p < P; p++) s = fmaf(opw[p * P + d], Wfuse[(T + p) * T + t], s);
        g_weff2[i] = s;
    }
    if (tid < T) {
        float s = 0.f;
#pragma unroll
        for (int p = 0; p < P; p++) s = fmaf(opb[p], Wfuse[(T + p) * T + tid], s);
        g_beff[tid] = s;
    }
}

// ---------------- K4: bi-GRU scan, one block per batch row ----------------
#define GRU_WSTRIDE 193
#define GRU_SM_FLOATS (2 * 64 * GRU_WSTRIDE + 2 * H + 2 * G)
__global__ void gru_kernel(const float* __restrict__ Whh_f, const float* __restrict__ Whh_b,
                           const float* __restrict__ bhh_f, const float* __restrict__ bhh_b) {
    extern __shared__ float sm[];
    float* whh0 = sm;                        // [64][193] transposed: [k*193 + g]
    float* whh1 = sm + 64 * GRU_WSTRIDE;
    float* h0 = whh1 + 64 * GRU_WSTRIDE;     // 64
    float* h1 = h0 + H;                      // 64
    float* gh0 = h1 + H;                     // 192
    float* gh1 = gh0 + G;                    // 192

    const int b = blockIdx.x;
    const int tid = threadIdx.x;             // 384
    const int dir = tid >= G;
    const int g = tid - dir * G;

    for (int i = tid; i < G * H; i += blockDim.x) {
        int gg = i >> 6, kk = i & 63;
        whh0[kk * GRU_WSTRIDE + gg] = Whh_f[i];
        whh1[kk * GRU_WSTRIDE + gg] = Whh_b[i];
    }
    if (tid < H) { h0[tid] = 0.f; h1[tid] = 0.f; }
    __syncthreads();

    const float bias = dir ? bhh_b[g] : bhh_f[g];
    float* whh = dir ? whh1 : whh0;
    float* hsh = dir ? h1 : h0;
    float* ghsh = dir ? gh1 : gh0;
    const float* xp = dir ? g_xp_b : g_xp_f;
    float* lout = g_lstm;

    for (int t = 0; t < S; t++) {
        const int te = dir ? (S - 1 - t) : t;
        // prefetch xp row (only consumers need it)
        float xrv = 0.f, xzv = 0.f, xnv = 0.f;
        if (g < H) {
            const float* xr = xp + ((size_t)b * S + te) * G;
            xrv = xr[g]; xzv = xr[H + g]; xnv = xr[2 * H + g];
        }
        // gh = h @ Whh^T + bhh
        float a0 = 0.f, a1 = 0.f, a2 = 0.f, a3 = 0.f;
#pragma unroll
        for (int k = 0; k < H; k += 4) {
            a0 = fmaf(whh[(k + 0) * GRU_WSTRIDE + g], hsh[k + 0], a0);
            a1 = fmaf(whh[(k + 1) * GRU_WSTRIDE + g], hsh[k + 1], a1);
            a2 = fmaf(whh[(k + 2) * GRU_WSTRIDE + g], hsh[k + 2], a2);
            a3 = fmaf(whh[(k + 3) * GRU_WSTRIDE + g], hsh[k + 3], a3);
        }
        ghsh[g] = (a0 + a1) + (a2 + a3) + bias;
        __syncthreads();
        if (g < H) {
            float r = sigmoidf_(xrv + ghsh[g]);
            float z = sigmoidf_(xzv + ghsh[H + g]);
            float n = tanhf(xnv + r * ghsh[2 * H + g]);
            float hn = (1.f - z) * n + z * hsh[g];
            hsh[g] = hn;
            lout[((size_t)b * S + te) * (2 * H) + dir * H + g] = hn;
        }
        __syncthreads();
    }
}

// ---------------- K5: attention (per batch, 32-query tile), AV written unprojected ----------------
#define KV_STRIDE 33
#define ATTN_SM_FLOATS (2 * S * KV_STRIDE + S + P + 256 + 8 * KV_STRIDE)
__global__ void attn_kernel() {
    extern __shared__ float sm[];
    float* Ksh = sm;                         // [512][33]
    float* Vsh = Ksh + S * KV_STRIDE;        // [512][33]
    float* psh = Vsh + S * KV_STRIDE;        // [512]
    float* qsh = psh + S;                    // [32]
    float* red = qsh + P;                    // [256]
    float* part = red + 256;                 // [8][33]

    const int qt = blockIdx.x;   // 0..15
    const int b = blockIdx.y;    // 0..63
    const int tid = threadIdx.x; // 256
    const float scale = 0.17677669529663689f; // 1/sqrt(32)

    for (int i = tid; i < S * P; i += 256) {
        int k = i >> 5, d = i & 31;
        const float* row = g_qkv + ((size_t)b * S + k) * (3 * P);
        Ksh[k * KV_STRIDE + d] = row[P + d];
        Vsh[k * KV_STRIDE + d] = row[2 * P + d];
    }
    __syncthreads();

    for (int qi = 0; qi < 32; qi++) {
        const int q = qt * 32 + qi;
        if (tid < P) qsh[tid] = g_qkv[((size_t)b * S + q) * (3 * P) + tid];
        __syncthreads();

        float lmax = -1e30f;
        for (int k = tid; k < S; k += 256) {
            float s = 0.f;
            const float* kr = Ksh + k * KV_STRIDE;
#pragma unroll
            for (int j = 0; j < P; j++) s = fmaf(qsh[j], kr[j], s);
            s *= scale;
            psh[k] = s;
            lmax = fmaxf(lmax, s);
        }
        red[tid] = lmax; __syncthreads();
        for (int st = 128; st > 0; st >>= 1) {
            if (tid < st) red[tid] = fmaxf(red[tid], red[tid + st]);
            __syncthreads();
        }
        const float m = red[0];
        __syncthreads();

        float lsum = 0.f;
        for (int k = tid; k < S; k += 256) {
            float e = __expf(psh[k] - m);
            psh[k] = e;
            lsum += e;
        }
        red[tid] = lsum; __syncthreads();
        for (int st = 128; st > 0; st >>= 1) {
            if (tid < st) red[tid] += red[tid + st];
            __syncthreads();
        }
        const float invZ = 1.0f / red[0];
        __syncthreads();

        const int d = tid & 31;
        const int kg = tid >> 5;  // 0..7
        float acc = 0.f;
        for (int k = kg * 64; k < kg * 64 + 64; k++)
            acc = fmaf(psh[k], Vsh[k * KV_STRIDE + d], acc);
        part[kg * KV_STRIDE + d] = acc;
        __syncthreads();
        if (tid < P) {
            float tot = 0.f;
#pragma unroll
            for (int kk = 0; kk < 8; kk++) tot += part[kk * KV_STRIDE + tid];
            g_av[((size_t)b * S + q) * P + tid] = tot * invZ;
        }
        __syncthreads();
    }
}

// ---------------- K6: emissions ----------------
__global__ void emis_kernel() {
    __shared__ float lrow[16 * 2 * H];  // 16 rows x 128
    __shared__ float arow[16 * P];      // 16 rows x 32
    __shared__ float w1[2 * H * T];
    __shared__ float w2[P * T];
    __shared__ float be[T];
    const int tid = threadIdx.x;        // 256
    const int r0 = blockIdx.x * 16;

    for (int i = tid; i < 16 * 2 * H; i += 256) lrow[i] = g_lstm[(size_t)r0 * 2 * H + i];
    for (int i = tid; i < 16 * P; i += 256) arow[i] = g_av[(size_t)r0 * P + i];
    for (int i = tid; i < 2 * H * T; i += 256) w1[i] = g_weff1[i];
    for (int i = tid; i < P * T; i += 256) w2[i] = g_weff2[i];
    if (tid < T) be[tid] = g_beff[tid];
    __syncthreads();

    const int rr = tid >> 4;
    const int t = tid & 15;
    float acc = be[t];
    const float* lr = lrow + rr * 2 * H;
    const float* ar = arow + rr * P;
#pragma unroll 8
    for (int j = 0; j < 2 * H; j++) acc = fmaf(lr[j], w1[j * T + t], acc);
#pragma unroll
    for (int dd = 0; dd < P; dd++) acc = fmaf(ar[dd], w2[dd * T + t], acc);
    g_emis[(size_t)(r0 + rr) * T + t] = acc;
}

// ---------------- K7: CRF per batch (one warp) ----------------
__global__ void crf_kernel(const int* __restrict__ targets, const float* __restrict__ crf_start,
                           const float* __restrict__ crf_end, const float* __restrict__ crf_trans) {
    __shared__ float tr[T * T];
    __shared__ float sc[T];
    __shared__ float st[T];
    __shared__ float en[T];
    __shared__ float s_num;
    const int b = blockIdx.x;
    const int tid = threadIdx.x;  // 32

    for (int i = tid; i < T * T; i += 32) tr[i] = crf_trans[i];
    if (tid < T) { st[tid] = crf_start[tid]; en[tid] = crf_end[tid]; }
    __syncthreads();

    // numerator
    const int* tg = targets + (size_t)b * S;
    float num = 0.f;
    for (int t = tid; t < S; t += 32) {
        int cur = tg[t];
        num += g_emis[((size_t)b * S + t) * T + cur];
        if (t < S - 1) num += tr[cur * T + tg[t + 1]];
    }
#pragma unroll
    for (int o = 16; o > 0; o >>= 1) num += __shfl_xor_sync(0xffffffffu, num, o);
    if (tid == 0) s_num = num + st[tg[0]] + en[tg[S - 1]];

    // forward algorithm
    if (tid < T) sc[tid] = st[tid] + g_emis[((size_t)b * S) * T + tid];
    __syncthreads();

    for (int t = 1; t < S; t++) {
        float nv = 0.f;
        if (tid < T) {
            float m = -1e30f;
#pragma unroll
            for (int i = 0; i < T; i++) m = fmaxf(m, sc[i] + tr[i * T + tid]);
            float s = 0.f;
#pragma unroll
            for (int i = 0; i < T; i++) s += __expf(sc[i] + tr[i * T + tid] - m);
            nv = m + __logf(s) + g_emis[((size_t)b * S + t) * T + tid];
        }
        __syncwarp();
        if (tid < T) sc[tid] = nv;
        __syncwarp();
    }

    float v = (tid < T) ? (sc[tid] + en[tid]) : -1e30f;
    float m = v;
#pragma unroll
    for (int o = 16; o > 0; o >>= 1) m = fmaxf(m, __shfl_xor_sync(0xffffffffu, m, o));
    float e = (tid < T) ? __expf(v - m) : 0.f;
#pragma unroll
    for (int o = 16; o > 0; o >>= 1) e += __shfl_xor_sync(0xffffffffu, e, o);
    __syncthreads();
    if (tid == 0) g_nll[b] = (m + __logf(e)) - s_num;
}

// ---------------- K8: final mean ----------------
__global__ void final_kernel(float* __restrict__ out) {
    __shared__ float red[B];
    red[threadIdx.x] = g_nll[threadIdx.x];
    __syncthreads();
    for (int st = 32; st > 0; st >>= 1) {
        if (threadIdx.x < st) red[threadIdx.x] += red[threadIdx.x + st];
        __syncthreads();
    }
    if (threadIdx.x == 0) out[0] = red[0] * (1.0f / B);
}

// ---------------- launch ----------------
extern "C" void kernel_launch(void* const* d_in, const int* in_sizes, int n_in,
                              void* d_out, int out_size) {
    const float* bert = (const float*)d_in[0];
    const float* input2 = (const float*)d_in[1];
    const int* targets = (const int*)d_in[2];
    const float* Wih_f = (const float*)d_in[3];
    const float* Whh_f = (const float*)d_in[4];
    const float* bih_f = (const float*)d_in[5];
    const float* bhh_f = (const float*)d_in[6];
    const float* Wih_b = (const float*)d_in[7];
    const float* Whh_b = (const float*)d_in[8];
    const float* bih_b = (const float*)d_in[9];
    const float* bhh_b = (const float*)d_in[10];
    const float* Wdense = (const float*)d_in[11];
    const float* in_proj_w = (const float*)d_in[12];
    const float* in_proj_b = (const float*)d_in[13];
    const float* out_proj_w = (const float*)d_in[14];
    const float* out_proj_b = (const float*)d_in[15];
    const float* Wfuse = (const float*)d_in[16];
    const float* crf_start = (const float*)d_in[17];
    const float* crf_end = (const float*)d_in[18];
    const float* crf_trans = (const float*)d_in[19];
    float* out = (float*)d_out;

    cudaFuncSetAttribute(gru_kernel, cudaFuncAttributeMaxDynamicSharedMemorySize,
                         GRU_SM_FLOATS * (int)sizeof(float));
    cudaFuncSetAttribute(attn_kernel, cudaFuncAttributeMaxDynamicSharedMemorySize,
                         ATTN_SM_FLOATS * (int)sizeof(float));

    // xp GEMMs
    gemm_xp<<<dim3((B * S) / 64, G / 64), 256>>>(bert, Wih_f, bih_f, 0);
    gemm_xp<<<dim3((B * S) / 64, G / 64), 256>>>(bert, Wih_b, bih_b, 1);
    // qkv
    {
        int total = B * S * 3 * P;
        qkv_kernel<<<(total + 255) / 256, 256>>>(input2, in_proj_w, in_proj_b);
    }
    // folded weights
    weff_kernel<<<1, 256>>>(Wdense, out_proj_w, out_proj_b, Wfuse);
    // GRU
    gru_kernel<<<B, 384, GRU_SM_FLOATS * (int)sizeof(float)>>>(Whh_f, Whh_b, bhh_f, bhh_b);
    // attention
    attn_kernel<<<dim3(S / 32, B), 256, ATTN_SM_FLOATS * (int)sizeof(float)>>>();
    // emissions
    emis_kernel<<<(B * S) / 16, 256>>>();
    // CRF
    crf_kernel<<<B, 32>>>(targets, crf_start, crf_end, crf_trans);
    // mean
    final_kernel<<<1, B>>>(out);
}

// round 2
// speedup vs baseline: 2.0172x; 2.0172x over previous
#include <cuda_runtime.h>
#include <cuda_bf16.h>
#include <math.h>
#include <stdint.h>

// Problem constants
#define B 64
#define S 512
#define E 768
#define H 64
#define G 192   // 3H
#define T 16
#define P 32

// ---------------- scratch ----------------
__device__ float g_xp_f[B * S * G];
__device__ float g_xp_b[B * S * G];
__device__ float g_lstm[B * S * 2 * H];
__device__ float g_qkv[B * S * 3 * P];
__device__ float g_av[B * S * P];
__device__ float g_emis[B * S * T];
__device__ float g_weff1T[T * 2 * H];   // [t][j]
__device__ float g_weff2T[T * P];       // [t][d]
__device__ float g_beff[T];
__device__ float g_nll[B];

__device__ __forceinline__ float sigmoidf_(float x) { return 1.0f / (1.0f + __expf(-x)); }
__device__ __forceinline__ uint32_t f2tf(float x) {
    uint32_t r; asm("cvt.rna.tf32.f32 %0, %1;" : "=r"(r) : "f"(x)); return r;
}

// =================================================================
// K1: xp = bert @ [Wih_f;Wih_b]^T + bias  via tf32 mma.sync
// M=32768, N=384, K=768.  Block 128x128x16, 8 warps, warp 64x32.
// =================================================================
#define SMS 24   // smem row stride (floats) — conflict-free fragment loads
__global__ void __launch_bounds__(256) gemm_xp_tc(
    const float* __restrict__ A,
    const float* __restrict__ Wf, const float* __restrict__ Wb,
    const float* __restrict__ bf, const float* __restrict__ bb)
{
    __shared__ uint32_t Asm[128 * SMS];
    __shared__ uint32_t Bsm[128 * SMS];
    const int tid = threadIdx.x;
    const int bm = blockIdx.y * 128;
    const int bn = blockIdx.x * 128;
    const int w = tid >> 5, lane = tid & 31;
    const int wm = (w >> 2) * 64, wn = (w & 3) * 32;
    const int grp = lane >> 2, tig = lane & 3;

    float acc[4][4][4];
#pragma unroll
    for (int mt = 0; mt < 4; mt++)
#pragma unroll
        for (int nt = 0; nt < 4; nt++)
#pragma unroll
            for (int d = 0; d < 4; d++) acc[mt][nt][d] = 0.0f;

    // loader: row = tid>>1 (0..127), two float4's at q = (tid&1)*2 + {0,1}
    const int lrow = tid >> 1;
    const int lq0 = (tid & 1) * 2;
    const float* Arow = A + (size_t)(bm + lrow) * E;
    const int nrow = bn + lrow;
    const float* Wrow = (nrow < G) ? (Wf + (size_t)nrow * E)
                                   : (Wb + (size_t)(nrow - G) * E);

    float4 pa[2], pb[2];
#pragma unroll
    for (int qq = 0; qq < 2; qq++) {
        pa[qq] = *(const float4*)(Arow + (lq0 + qq) * 4);
        pb[qq] = *(const float4*)(Wrow + (lq0 + qq) * 4);
    }
    // store tile 0
#pragma unroll
    for (int qq = 0; qq < 2; qq++) {
        const float* va = (const float*)&pa[qq];
        const float* vb = (const float*)&pb[qq];
#pragma unroll
        for (int j = 0; j < 4; j++) {
            int kk = (lq0 + qq) * 4 + j;
            int gg = kk >> 3, c = kk & 7;
            int st = 2 * (c & 3) + (c >> 2);
            Asm[lrow * SMS + gg * 8 + st] = f2tf(va[j]);
            Bsm[lrow * SMS + gg * 8 + st] = f2tf(vb[j]);
        }
    }
    __syncthreads();

    for (int kt = 0; kt < 48; kt++) {
        if (kt < 47) {
            int kn = (kt + 1) * 16;
#pragma unroll
            for (int qq = 0; qq < 2; qq++) {
                pa[qq] = *(const float4*)(Arow + kn + (lq0 + qq) * 4);
                pb[qq] = *(const float4*)(Wrow + kn + (lq0 + qq) * 4);
            }
        }
#pragma unroll
        for (int gg = 0; gg < 2; gg++) {
            uint32_t afr[4][4], bfr[4][2];
#pragma unroll
            for (int mt = 0; mt < 4; mt++) {
                const uint32_t* p = &Asm[(wm + mt * 16 + grp) * SMS + gg * 8 + 2 * tig];
                afr[mt][0] = p[0]; afr[mt][2] = p[1];
                const uint32_t* p2 = p + 8 * SMS;
                afr[mt][1] = p2[0]; afr[mt][3] = p2[1];
            }
#pragma unroll
            for (int nt = 0; nt < 4; nt++) {
                const uint32_t* p = &Bsm[(wn + nt * 8 + grp) * SMS + gg * 8 + 2 * tig];
                bfr[nt][0] = p[0]; bfr[nt][1] = p[1];
            }
#pragma unroll
            for (int mt = 0; mt < 4; mt++)
#pragma unroll
                for (int nt = 0; nt < 4; nt++) {
                    asm volatile(
                        "mma.sync.aligned.m16n8k8.row.col.f32.tf32.tf32.f32 "
                        "{%0,%1,%2,%3},{%4,%5,%6,%7},{%8,%9},{%0,%1,%2,%3};"
                        : "+f"(acc[mt][nt][0]), "+f"(acc[mt][nt][1]),
                          "+f"(acc[mt][nt][2]), "+f"(acc[mt][nt][3])
                        : "r"(afr[mt][0]), "r"(afr[mt][1]), "r"(afr[mt][2]), "r"(afr[mt][3]),
                          "r"(bfr[nt][0]), "r"(bfr[nt][1]));
                }
        }
        __syncthreads();
        if (kt < 47) {
#pragma unroll
            for (int qq = 0; qq < 2; qq++) {
                const float* va = (const float*)&pa[qq];
                const float* vb = (const float*)&pb[qq];
#pragma unroll
                for (int j = 0; j < 4; j++) {
                    int kk = (lq0 + qq) * 4 + j;
                    int gg = kk >> 3, c = kk & 7;
                    int st = 2 * (c & 3) + (c >> 2);
                    Asm[lrow * SMS + gg * 8 + st] = f2tf(va[j]);
                    Bsm[lrow * SMS + gg * 8 + st] = f2tf(vb[j]);
                }
            }
            __syncthreads();
        }
    }

    // epilogue
#pragma unroll
    for (int mt = 0; mt < 4; mt++) {
        int mlo = bm + wm + mt * 16 + grp;
#pragma unroll
        for (int nt = 0; nt < 4; nt++) {
            int n = bn + wn + nt * 8 + 2 * tig;
            float* dst; const float* bp; int nn;
            if (n < G) { dst = g_xp_f; bp = bf; nn = n; }
            else       { dst = g_xp_b; bp = bb; nn = n - G; }
            float b0 = __ldg(bp + nn), b1 = __ldg(bp + nn + 1);
            float2 lo = make_float2(acc[mt][nt][0] + b0, acc[mt][nt][1] + b1);
            float2 hi = make_float2(acc[mt][nt][2] + b0, acc[mt][nt][3] + b1);
            *(float2*)(dst + (size_t)mlo * G + nn) = lo;
            *(float2*)(dst + (size_t)(mlo + 8) * G + nn) = hi;
        }
    }
}

// =================================================================
// K2: qkv = input2 @ in_proj_w^T + in_proj_b (vectorized)
// =================================================================
__global__ void qkv_kernel(const float* __restrict__ in2, const float* __restrict__ W,
                           const float* __restrict__ bias) {
    int idx = blockIdx.x * blockDim.x + threadIdx.x;
    if (idx >= B * S * 3 * P) return;
    int m = idx / (3 * P);
    int n = idx % (3 * P);
    const float4* x = (const float4*)(in2 + (size_t)m * P);
    const float4* wv = (const float4*)(W + (size_t)n * P);
    float acc = bias[n];
#pragma unroll
    for (int k = 0; k < 8; k++) {
        float4 a = __ldg(x + k), b = __ldg(wv + k);
        acc = fmaf(a.x, b.x, acc); acc = fmaf(a.y, b.y, acc);
        acc = fmaf(a.z, b.z, acc); acc = fmaf(a.w, b.w, acc);
    }
    g_qkv[idx] = acc;
}

// ---------------- K3: folded weights (transposed layout) ----------------
__global__ void weff_kernel(const float* __restrict__ Wdense, const float* __restrict__ opw,
                            const float* __restrict__ opb, const float* __restrict__ Wfuse) {
    int tid = threadIdx.x;
    for (int i = tid; i < 2 * H * T; i += blockDim.x) {
        int t = i >> 7, j = i & 127;
        float s = 0.f;
#pragma unroll
        for (int u = 0; u < T; u++) s = fmaf(Wdense[j * T + u], Wfuse[u * T + t], s);
        g_weff1T[t * 2 * H + j] = s;
    }
    for (int i = tid; i < P * T; i += blockDim.x) {
        int t = i >> 5, d = i & 31;
        float s = 0.f;
#pragma unroll
        for (int p = 0; p < P; p++) s = fmaf(opw[p * P + d], Wfuse[(T + p) * T + t], s);
        g_weff2T[t * P + d] = s;
    }
    if (tid < T) {
        float s = 0.f;
#pragma unroll
        for (int p = 0; p < P; p++) s = fmaf(opb[p], Wfuse[(T + p) * T + tid], s);
        g_beff[tid] = s;
    }
}

// =================================================================
// K4: fused GRU (blocks 0..127) + flash attention (blocks 128..639)
// =================================================================
struct SmemU {
    union {
        struct { float hsh[64]; float ghsh[192]; } gru;
        struct { float Ks[64 * 36]; float Vs[64 * 36]; float psh[64 * 68]; } at;
    };
};

__global__ void __launch_bounds__(256) gru_attn_kernel(
    const float* __restrict__ Whh_f, const float* __restrict__ Whh_b,
    const float* __restrict__ bhh_f, const float* __restrict__ bhh_b)
{
    __shared__ SmemU sm;
    const int tid = threadIdx.x;

    if (blockIdx.x < 128) {
        // ---------------- GRU ----------------
        const int b = blockIdx.x >> 1;
        const int dir = blockIdx.x & 1;
        float* hsh = sm.gru.hsh;
        float* ghsh = sm.gru.ghsh;
        const bool act = (tid < G);
        float wreg[64];
        float bias = 0.f;
        if (act) {
            const float* Whh = dir ? Whh_b : Whh_f;
            const float4* wr = (const float4*)(Whh + (size_t)tid * H);
#pragma unroll
            for (int i = 0; i < 16; i++) {
                float4 v = __ldg(wr + i);
                wreg[4 * i] = v.x; wreg[4 * i + 1] = v.y;
                wreg[4 * i + 2] = v.z; wreg[4 * i + 3] = v.w;
            }
            bias = (dir ? bhh_b : bhh_f)[tid];
        }
        if (tid < H) hsh[tid] = 0.f;
        __syncthreads();

        const float* xp = (dir ? g_xp_b : g_xp_f) + (size_t)b * S * G;
        float xr = 0.f, xz = 0.f, xn = 0.f;
        if (tid < H) {
            const float* xrow = xp + (size_t)(dir ? (S - 1) : 0) * G;
            xr = xrow[tid]; xz = xrow[H + tid]; xn = xrow[2 * H + tid];
        }
        for (int t = 0; t < S; t++) {
            const int te = dir ? (S - 1 - t) : t;
            if (act) {
                float a0 = bias, a1 = 0.f, a2 = 0.f, a3 = 0.f;
                const float4* hv = (const float4*)hsh;
#pragma unroll
                for (int i = 0; i < 16; i++) {
                    float4 h4 = hv[i];
                    a0 = fmaf(wreg[4 * i], h4.x, a0);
                    a1 = fmaf(wreg[4 * i + 1], h4.y, a1);
                    a2 = fmaf(wreg[4 * i + 2], h4.z, a2);
                    a3 = fmaf(wreg[4 * i + 3], h4.w, a3);
                }
                ghsh[tid] = (a0 + a1) + (a2 + a3);
            }
            __syncthreads();
            float nxr = 0.f, nxz = 0.f, nxn = 0.f;
            if (t < S - 1 && tid < H) {
                const float* xrow = xp + (size_t)(dir ? (S - 2 - t) : (t + 1)) * G;
                nxr = xrow[tid]; nxz = xrow[H + tid]; nxn = xrow[2 * H + tid];
            }
            if (tid < H) {
                float r = sigmoidf_(xr + ghsh[tid]);
                float z = sigmoidf_(xz + ghsh[H + tid]);
                float nw = tanhf(xn + r * ghsh[2 * H + tid]);
                float hn = (1.f - z) * nw + z * hsh[tid];
                hsh[tid] = hn;
                g_lstm[((size_t)b * S + te) * (2 * H) + dir * H + tid] = hn;
            }
            __syncthreads();
            xr = nxr; xz = nxz; xn = nxn;
        }
    } else {
        // ---------------- flash attention ----------------
        const int bid = blockIdx.x - 128;
        const int qt = bid & 7, b = bid >> 3;
        float* Ks = sm.at.Ks;
        float* Vs = sm.at.Vs;
        float* psh = sm.at.psh;
        const int q = tid >> 2, kg = tid & 3;
        const int qg = qt * 64 + q;
        const float scale = 0.17677669529663689f;

        float4 qv[8];
        {
            const float4* qp = (const float4*)(g_qkv + ((size_t)b * S + qg) * (3 * P));
#pragma unroll
            for (int i = 0; i < 8; i++) qv[i] = __ldg(qp + i);
        }
        float av0[4] = {0.f, 0.f, 0.f, 0.f}, av1[4] = {0.f, 0.f, 0.f, 0.f};
        float mrun = -1e30f, lrun = 0.f;

        for (int kt = 0; kt < 8; kt++) {
            __syncthreads();
            for (int i = tid; i < 64 * P; i += 256) {
                int row = i >> 5, d = i & 31;
                const float* base = g_qkv + ((size_t)b * S + kt * 64 + row) * (3 * P);
                Ks[row * 36 + d] = base[P + d];
                Vs[row * 36 + d] = base[2 * P + d];
            }
            __syncthreads();

            float sv[16];
            float tmax = -1e30f;
#pragma unroll
            for (int kl = 0; kl < 16; kl++) {
                int k = kg + kl * 4;
                const float4* kr = (const float4*)(Ks + k * 36);
                float d0 = 0.f, d1 = 0.f, d2 = 0.f, d3 = 0.f;
#pragma unroll
                for (int i = 0; i < 8; i += 4) {
                    float4 k0 = kr[i], k1 = kr[i + 1], k2 = kr[i + 2], k3 = kr[i + 3];
                    d0 = fmaf(qv[i].x, k0.x, d0); d0 = fmaf(qv[i].y, k0.y, d0);
                    d0 = fmaf(qv[i].z, k0.z, d0); d0 = fmaf(qv[i].w, k0.w, d0);
                    d1 = fmaf(qv[i+1].x, k1.x, d1); d1 = fmaf(qv[i+1].y, k1.y, d1);
                    d1 = fmaf(qv[i+1].z, k1.z, d1); d1 = fmaf(qv[i+1].w, k1.w, d1);
                    d2 = fmaf(qv[i+2].x, k2.x, d2); d2 = fmaf(qv[i+2].y, k2.y, d2);
                    d2 = fmaf(qv[i+2].z, k2.z, d2); d2 = fmaf(qv[i+2].w, k2.w, d2);
                    d3 = fmaf(qv[i+3].x, k3.x, d3); d3 = fmaf(qv[i+3].y, k3.y, d3);
                    d3 = fmaf(qv[i+3].z, k3.z, d3); d3 = fmaf(qv[i+3].w, k3.w, d3);
                }
                sv[kl] = ((d0 + d1) + (d2 + d3)) * scale;
                tmax = fmaxf(tmax, sv[kl]);
            }
            tmax = fmaxf(tmax, __shfl_xor_sync(0xffffffffu, tmax, 1));
            tmax = fmaxf(tmax, __shfl_xor_sync(0xffffffffu, tmax, 2));
            float mnew = fmaxf(mrun, tmax);
            float corr = __expf(mrun - mnew);
            float tsum = 0.f;
#pragma unroll
            for (int kl = 0; kl < 16; kl++) {
                float e = __expf(sv[kl] - mnew);
                psh[q * 68 + kg + kl * 4] = e;
                tsum += e;
            }
            tsum += __shfl_xor_sync(0xffffffffu, tsum, 1);
            tsum += __shfl_xor_sync(0xffffffffu, tsum, 2);
            lrun = lrun * corr + tsum;
            mrun = mnew;
#pragma unroll
            for (int j = 0; j < 4; j++) { av0[j] *= corr; av1[j] *= corr; }
            __syncwarp();
#pragma unroll 4
            for (int k = 0; k < 64; k++) {
                float p = psh[q * 68 + k];
                const float4* vr = (const float4*)(Vs + k * 36 + kg * 8);
                float4 v0 = vr[0], v1 = vr[1];
                av0[0] = fmaf(p, v0.x, av0[0]); av0[1] = fmaf(p, v0.y, av0[1]);
                av0[2] = fmaf(p, v0.z, av0[2]); av0[3] = fmaf(p, v0.w, av0[3]);
                av1[0] = fmaf(p, v1.x, av1[0]); av1[1] = fmaf(p, v1.y, av1[1]);
                av1[2] = fmaf(p, v1.z, av1[2]); av1[3] = fmaf(p, v1.w, av1[3]);
            }
            __syncwarp();
        }
        float inv = 1.0f / lrun;
        float* op = g_av + ((size_t)b * S + qg) * P + kg * 8;
        *(float4*)(op) = make_float4(av0[0] * inv, av0[1] * inv, av0[2] * inv, av0[3] * inv);
        *(float4*)(op + 4) = make_float4(av1[0] * inv, av1[1] * inv, av1[2] * inv, av1[3] * inv);
    }
}

// ---------------- K5: emissions ----------------
__global__ void __launch_bounds__(256) emis_kernel() {
    __shared__ float lrow[16 * 2 * H];
    __shared__ float arow[16 * P];
    __shared__ float w1s[T * 132];
    __shared__ float w2s[T * 36];
    __shared__ float bes[T];
    const int tid = threadIdx.x;
    const int r0 = blockIdx.x * 16;

    for (int i = tid; i < 16 * 2 * H; i += 256) lrow[i] = g_lstm[(size_t)r0 * 2 * H + i];
    for (int i = tid; i < 16 * P; i += 256) arow[i] = g_av[(size_t)r0 * P + i];
    for (int i = tid; i < T * 2 * H; i += 256) {
        int t = i >> 7, j = i & 127;
        w1s[t * 132 + j] = g_weff1T[i];
    }
    for (int i = tid; i < T * P; i += 256) {
        int t = i >> 5, d = i & 31;
        w2s[t * 36 + d] = g_weff2T[i];
    }
    if (tid < T) bes[tid] = g_beff[tid];
    __syncthreads();

    const int rr = tid >> 4;
    const int t = tid & 15;
    float acc = bes[t];
    const float4* lr = (const float4*)(lrow + rr * 2 * H);
    const float4* w1 = (const float4*)(w1s + t * 132);
#pragma unroll
    for (int i = 0; i < 32; i++) {
        float4 a = lr[i], wv = w1[i];
        acc = fmaf(a.x, wv.x, acc); acc = fmaf(a.y, wv.y, acc);
        acc = fmaf(a.z, wv.z, acc); acc = fmaf(a.w, wv.w, acc);
    }
    const float4* ar = (const float4*)(arow + rr * P);
    const float4* w2 = (const float4*)(w2s + t * 36);
#pragma unroll
    for (int i = 0; i < 8; i++) {
        float4 a = ar[i], wv = w2[i];
        acc = fmaf(a.x, wv.x, acc); acc = fmaf(a.y, wv.y, acc);
        acc = fmaf(a.z, wv.z, acc); acc = fmaf(a.w, wv.w, acc);
    }
    g_emis[(size_t)(r0 + rr) * T + t] = acc;
}

// ---------------- K6: CRF per batch (one warp, all 32 lanes) ----------------
__global__ void crf_kernel(const int* __restrict__ targets, const float* __restrict__ crf_start,
                           const float* __restrict__ crf_end, const float* __restrict__ crf_trans) {
    __shared__ float tr[T * 17];
    __shared__ float sc[T];
    __shared__ float st[T];
    __shared__ float en[T];
    __shared__ float s_num;
    const int b = blockIdx.x;
    const int lane = threadIdx.x;
    const int j = lane & 15, half = lane >> 4;

    for (int i = lane; i < T * T; i += 32) tr[(i >> 4) * 17 + (i & 15)] = crf_trans[i];
    if (lane < T) { st[lane] = crf_start[lane]; en[lane] = crf_end[lane]; }
    __syncthreads();

    // numerator
    const int* tg = targets + (size_t)b * S;
    float num = 0.f;
    for (int t = lane; t < S; t += 32) {
        int cur = tg[t];
        num += g_emis[((size_t)b * S + t) * T + cur];
        if (t < S - 1) num += tr[cur * 17 + tg[t + 1]];
    }
#pragma unroll
    for (int o = 16; o > 0; o >>= 1) num += __shfl_xor_sync(0xffffffffu, num, o);
    if (lane == 0) s_num = num + st[tg[0]] + en[tg[S - 1]];

    if (lane < T) sc[lane] = st[lane] + g_emis[((size_t)b * S) * T + lane];
    __syncwarp();
    __syncthreads();

    float em = g_emis[((size_t)b * S + 1) * T + j];
    for (int t = 1; t < S; t++) {
        float em_next = (t < S - 1) ? g_emis[((size_t)b * S + t + 1) * T + j] : 0.f;
        float x[8];
        float m = -1e30f;
#pragma unroll
        for (int i8 = 0; i8 < 8; i8++) {
            int i = half * 8 + i8;
            x[i8] = sc[i] + tr[i * 17 + j];
            m = fmaxf(m, x[i8]);
        }
        float ssum = 0.f;
#pragma unroll
        for (int i8 = 0; i8 < 8; i8++) ssum += __expf(x[i8] - m);
        float mo = __shfl_xor_sync(0xffffffffu, m, 16);
        float so = __shfl_xor_sync(0xffffffffu, ssum, 16);
        float m2 = fmaxf(m, mo);
        float stot = ssum * __expf(m - m2) + so * __expf(mo - m2);
        float nv = m2 + __logf(stot) + em;
        __syncwarp();
        if (half == 0) sc[j] = nv;
        __syncwarp();
        em = em_next;
    }

    float v = (lane < T) ? (sc[lane] + en[lane]) : -1e30f;
    float m = v;
#pragma unroll
    for (int o = 16; o > 0; o >>= 1) m = fmaxf(m, __shfl_xor_sync(0xffffffffu, m, o));
    float e = (lane < T) ? __expf(v - m) : 0.f;
#pragma unroll
    for (int o = 16; o > 0; o >>= 1) e += __shfl_xor_sync(0xffffffffu, e, o);
    __syncthreads();
    if (lane == 0) g_nll[b] = (m + __logf(e)) - s_num;
}

// ---------------- K7: final mean ----------------
__global__ void final_kernel(float* __restrict__ out) {
    __shared__ float red[B];
    red[threadIdx.x] = g_nll[threadIdx.x];
    __syncthreads();
    for (int stp = 32; stp > 0; stp >>= 1) {
        if (threadIdx.x < stp) red[threadIdx.x] += red[threadIdx.x + stp];
        __syncthreads();
    }
    if (threadIdx.x == 0) out[0] = red[0] * (1.0f / B);
}

// ---------------- launch ----------------
extern "C" void kernel_launch(void* const* d_in, const int* in_sizes, int n_in,
                              void* d_out, int out_size) {
    const float* bert = (const float*)d_in[0];
    const float* input2 = (const float*)d_in[1];
    const int* targets = (const int*)d_in[2];
    const float* Wih_f = (const float*)d_in[3];
    const float* Whh_f = (const float*)d_in[4];
    const float* bih_f = (const float*)d_in[5];
    const float* bhh_f = (const float*)d_in[6];
    const float* Wih_b = (const float*)d_in[7];
    const float* Whh_b = (const float*)d_in[8];
    const float* bih_b = (const float*)d_in[9];
    const float* bhh_b = (const float*)d_in[10];
    const float* Wdense = (const float*)d_in[11];
    const float* in_proj_w = (const float*)d_in[12];
    const float* in_proj_b = (const float*)d_in[13];
    const float* out_proj_w = (const float*)d_in[14];
    const float* out_proj_b = (const float*)d_in[15];
    const float* Wfuse = (const float*)d_in[16];
    const float* crf_start = (const float*)d_in[17];
    const float* crf_end = (const float*)d_in[18];
    const float* crf_trans = (const float*)d_in[19];
    float* out = (float*)d_out;

    gemm_xp_tc<<<dim3(3, 256), 256>>>(bert, Wih_f, Wih_b, bih_f, bih_b);
    {
        int total = B * S * 3 * P;
        qkv_kernel<<<(total + 255) / 256, 256>>>(input2, in_proj_w, in_proj_b);
    }
    weff_kernel<<<1, 256>>>(Wdense, out_proj_w, out_proj_b, Wfuse);
    gru_attn_kernel<<<128 + 512, 256>>>(Whh_f, Whh_b, bhh_f, bhh_b);
    emis_kernel<<<(B * S) / 16, 256>>>();
    crf_kernel<<<B, 32>>>(targets, crf_start, crf_end, crf_trans);
    final_kernel<<<1, B>>>(out);
}

// round 3
// speedup vs baseline: 2.6293x; 1.3034x over previous
#include <cuda_runtime.h>
#include <cuda_bf16.h>
#include <math.h>
#include <stdint.h>

// Problem constants
#define B 64
#define S 512
#define E 768
#define H 64
#define G 192   // 3H
#define T 16
#define P 32

// ---------------- scratch ----------------
__device__ float g_xp_f[B * S * G];
__device__ float g_xp_b[B * S * G];
__device__ float g_lstm[B * S * 2 * H];
__device__ float g_qkv[B * S * 3 * P];
__device__ float g_av[B * S * P];
__device__ float g_emis[B * S * T];
__device__ float g_weff1T[T * 2 * H];
__device__ float g_weff2T[T * P];
__device__ float g_beff[T];
__device__ float g_nll[B];

__device__ __forceinline__ float sigmoidf_(float x) { return 1.0f / (1.0f + __expf(-x)); }
__device__ __forceinline__ float tanh_fast(float x) {
    float y; asm("tanh.approx.f32 %0, %1;" : "=f"(y) : "f"(x)); return y;
}
__device__ __forceinline__ void cp16(uint32_t s, const void* g) {
    asm volatile("cp.async.cg.shared.global [%0], [%1], 16;\n" :: "r"(s), "l"(g));
}
__device__ __forceinline__ void cp_commit() { asm volatile("cp.async.commit_group;\n"); }
template <int N> __device__ __forceinline__ void cp_wait() {
    asm volatile("cp.async.wait_group %0;\n" :: "n"(N));
}

// =================================================================
// K2 fused: gemm_xp (blocks 0..767) + flash attention (768..1279)
// GEMM: xp = bert @ [Wih_f;Wih_b]^T + bias, tf32 mma, cp.async 2-stage
// M=32768, N=384, K=768; BM=128, BN=128, BK=32.
// =================================================================
#define AST 36                       // smem row stride (floats), conflict-free frags
#define STAGE_F (2 * 128 * AST)      // floats per stage (A + B)
#define GEMM_BLOCKS 768
#define DSM_BYTES (2 * STAGE_F * 4)  // 73728

__global__ void __launch_bounds__(256) gemm_attn_kernel(
    const float* __restrict__ A,
    const float* __restrict__ Wf, const float* __restrict__ Wb,
    const float* __restrict__ bf, const float* __restrict__ bb)
{
    extern __shared__ __align__(16) float dsm[];
    const int tid = threadIdx.x;

    if (blockIdx.x < GEMM_BLOCKS) {
        // ---------------- GEMM ----------------
        const int bn = (blockIdx.x % 3) * 128;
        const int bm = (blockIdx.x / 3) * 128;
        const int w = tid >> 5, lane = tid & 31;
        const int wm = (w >> 2) * 64, wn = (w & 3) * 32;
        const int grp = lane >> 2, tig = lane & 3;

        // loader mapping: 4 tasks/thread per operand; row = tid>>3 + 32*i, c4 = tid&7
        const int lr = tid >> 3, c4 = tid & 7;
        const float* aptr[4];
        const float* wptr[4];
        uint32_t adst[2][4], bdst[2][4];
#pragma unroll
        for (int i = 0; i < 4; i++) {
            int row = lr + 32 * i;
            aptr[i] = A + (size_t)(bm + row) * E + c4 * 4;
            int nrow = bn + row;
            wptr[i] = (nrow < G) ? (Wf + (size_t)nrow * E + c4 * 4)
                                 : (Wb + (size_t)(nrow - G) * E + c4 * 4);
#pragma unroll
            for (int s = 0; s < 2; s++) {
                adst[s][i] = (uint32_t)__cvta_generic_to_shared(
                    dsm + s * STAGE_F + row * AST + c4 * 4);
                bdst[s][i] = (uint32_t)__cvta_generic_to_shared(
                    dsm + s * STAGE_F + 128 * AST + row * AST + c4 * 4);
            }
        }

        float acc[4][4][4];
#pragma unroll
        for (int mt = 0; mt < 4; mt++)
#pragma unroll
            for (int nt = 0; nt < 4; nt++)
#pragma unroll
                for (int d = 0; d < 4; d++) acc[mt][nt][d] = 0.0f;

        // prologue: issue tiles 0,1
#pragma unroll
        for (int i = 0; i < 4; i++) { cp16(adst[0][i], aptr[i]); cp16(bdst[0][i], wptr[i]); }
        cp_commit();
#pragma unroll
        for (int i = 0; i < 4; i++) { cp16(adst[1][i], aptr[i] + 32); cp16(bdst[1][i], wptr[i] + 32); }
        cp_commit();

        for (int kt = 0; kt < 24; kt++) {
            if (kt < 23) cp_wait<1>(); else cp_wait<0>();
            __syncthreads();

            const int s = kt & 1;
            const uint32_t* As = (const uint32_t*)(dsm + s * STAGE_F);
            const uint32_t* Bs = (const uint32_t*)(dsm + s * STAGE_F + 128 * AST);
#pragma unroll
            for (int ks = 0; ks < 4; ks++) {
                const int ko = ks * 8;
                uint32_t afr[4][4], bfr[4][2];
#pragma unroll
                for (int mt = 0; mt < 4; mt++) {
                    const uint32_t* p = As + (wm + mt * 16 + grp) * AST + ko + tig;
                    afr[mt][0] = p[0];
                    afr[mt][2] = p[4];
                    afr[mt][1] = p[8 * AST];
                    afr[mt][3] = p[8 * AST + 4];
                }
#pragma unroll
                for (int nt = 0; nt < 4; nt++) {
                    const uint32_t* p = Bs + (wn + nt * 8 + grp) * AST + ko + tig;
                    bfr[nt][0] = p[0];
                    bfr[nt][1] = p[4];
                }
#pragma unroll
                for (int mt = 0; mt < 4; mt++)
#pragma unroll
                    for (int nt = 0; nt < 4; nt++) {
                        asm volatile(
                            "mma.sync.aligned.m16n8k8.row.col.f32.tf32.tf32.f32 "
                            "{%0,%1,%2,%3},{%4,%5,%6,%7},{%8,%9},{%0,%1,%2,%3};"
                            : "+f"(acc[mt][nt][0]), "+f"(acc[mt][nt][1]),
                              "+f"(acc[mt][nt][2]), "+f"(acc[mt][nt][3])
                            : "r"(afr[mt][0]), "r"(afr[mt][1]), "r"(afr[mt][2]), "r"(afr[mt][3]),
                              "r"(bfr[nt][0]), "r"(bfr[nt][1]));
                    }
            }
            __syncthreads();
            if (kt + 2 < 24) {
                const int kn = (kt + 2) * 32;
#pragma unroll
                for (int i = 0; i < 4; i++) {
                    cp16(adst[s][i], aptr[i] + kn);
                    cp16(bdst[s][i], wptr[i] + kn);
                }
                cp_commit();
            }
        }

        // epilogue
#pragma unroll
        for (int mt = 0; mt < 4; mt++) {
            int mlo = bm + wm + mt * 16 + grp;
#pragma unroll
            for (int nt = 0; nt < 4; nt++) {
                int n = bn + wn + nt * 8 + 2 * tig;
                float* dst; const float* bp; int nn;
                if (n < G) { dst = g_xp_f; bp = bf; nn = n; }
                else       { dst = g_xp_b; bp = bb; nn = n - G; }
                float b0 = __ldg(bp + nn), b1 = __ldg(bp + nn + 1);
                *(float2*)(dst + (size_t)mlo * G + nn) =
                    make_float2(acc[mt][nt][0] + b0, acc[mt][nt][1] + b1);
                *(float2*)(dst + (size_t)(mlo + 8) * G + nn) =
                    make_float2(acc[mt][nt][2] + b0, acc[mt][nt][3] + b1);
            }
        }
    } else {
        // ---------------- flash attention ----------------
        const int bid = blockIdx.x - GEMM_BLOCKS;
        const int qt = bid & 7, b = bid >> 3;
        float* Ks = dsm;                  // [64][36]
        float* Vs = dsm + 64 * 36;        // [64][36]
        float* psh = dsm + 2 * 64 * 36;   // [64][68]
        const int q = tid >> 2, kg = tid & 3;
        const int qg = qt * 64 + q;
        const float scale = 0.17677669529663689f;

        float4 qv[8];
        {
            const float4* qp = (const float4*)(g_qkv + ((size_t)b * S + qg) * (3 * P));
#pragma unroll
            for (int i = 0; i < 8; i++) qv[i] = __ldg(qp + i);
        }
        float av0[4] = {0.f, 0.f, 0.f, 0.f}, av1[4] = {0.f, 0.f, 0.f, 0.f};
        float mrun = -1e30f, lrun = 0.f;

        for (int kt = 0; kt < 8; kt++) {
            __syncthreads();
            for (int i = tid; i < 64 * P; i += 256) {
                int row = i >> 5, d = i & 31;
                const float* base = g_qkv + ((size_t)b * S + kt * 64 + row) * (3 * P);
                Ks[row * 36 + d] = base[P + d];
                Vs[row * 36 + d] = base[2 * P + d];
            }
            __syncthreads();

            float sv[16];
            float tmax = -1e30f;
#pragma unroll
            for (int kl = 0; kl < 16; kl++) {
                int k = kg + kl * 4;
                const float4* kr = (const float4*)(Ks + k * 36);
                float d0 = 0.f, d1 = 0.f, d2 = 0.f, d3 = 0.f;
#pragma unroll
                for (int i = 0; i < 8; i += 4) {
                    float4 k0 = kr[i], k1 = kr[i + 1], k2 = kr[i + 2], k3 = kr[i + 3];
                    d0 = fmaf(qv[i].x, k0.x, d0); d0 = fmaf(qv[i].y, k0.y, d0);
                    d0 = fmaf(qv[i].z, k0.z, d0); d0 = fmaf(qv[i].w, k0.w, d0);
                    d1 = fmaf(qv[i+1].x, k1.x, d1); d1 = fmaf(qv[i+1].y, k1.y, d1);
                    d1 = fmaf(qv[i+1].z, k1.z, d1); d1 = fmaf(qv[i+1].w, k1.w, d1);
                    d2 = fmaf(qv[i+2].x, k2.x, d2); d2 = fmaf(qv[i+2].y, k2.y, d2);
                    d2 = fmaf(qv[i+2].z, k2.z, d2); d2 = fmaf(qv[i+2].w, k2.w, d2);
                    d3 = fmaf(qv[i+3].x, k3.x, d3); d3 = fmaf(qv[i+3].y, k3.y, d3);
                    d3 = fmaf(qv[i+3].z, k3.z, d3); d3 = fmaf(qv[i+3].w, k3.w, d3);
                }
                sv[kl] = ((d0 + d1) + (d2 + d3)) * scale;
                tmax = fmaxf(tmax, sv[kl]);
            }
            tmax = fmaxf(tmax, __shfl_xor_sync(0xffffffffu, tmax, 1));
            tmax = fmaxf(tmax, __shfl_xor_sync(0xffffffffu, tmax, 2));
            float mnew = fmaxf(mrun, tmax);
            float corr = __expf(mrun - mnew);
            float tsum = 0.f;
#pragma unroll
            for (int kl = 0; kl < 16; kl++) {
                float e = __expf(sv[kl] - mnew);
                psh[q * 68 + kg + kl * 4] = e;
                tsum += e;
            }
            tsum += __shfl_xor_sync(0xffffffffu, tsum, 1);
            tsum += __shfl_xor_sync(0xffffffffu, tsum, 2);
            lrun = lrun * corr + tsum;
            mrun = mnew;
#pragma unroll
            for (int j = 0; j < 4; j++) { av0[j] *= corr; av1[j] *= corr; }
            __syncwarp();
#pragma unroll 4
            for (int k = 0; k < 64; k++) {
                float p = psh[q * 68 + k];
                const float4* vr = (const float4*)(Vs + k * 36 + kg * 8);
                float4 v0 = vr[0], v1 = vr[1];
                av0[0] = fmaf(p, v0.x, av0[0]); av0[1] = fmaf(p, v0.y, av0[1]);
                av0[2] = fmaf(p, v0.z, av0[2]); av0[3] = fmaf(p, v0.w, av0[3]);
                av1[0] = fmaf(p, v1.x, av1[0]); av1[1] = fmaf(p, v1.y, av1[1]);
                av1[2] = fmaf(p, v1.z, av1[2]); av1[3] = fmaf(p, v1.w, av1[3]);
            }
            __syncwarp();
        }
        float inv = 1.0f / lrun;
        float* op = g_av + ((size_t)b * S + qg) * P + kg * 8;
        *(float4*)(op) = make_float4(av0[0] * inv, av0[1] * inv, av0[2] * inv, av0[3] * inv);
        *(float4*)(op + 4) = make_float4(av1[0] * inv, av1[1] * inv, av1[2] * inv, av1[3] * inv);
    }
}

// =================================================================
// K1: qkv + folded weights (fused; weff runs as the extra last block)
// =================================================================
#define QKV_BLOCKS ((B * S * 3 * P) / 256)
__global__ void qkv_weff_kernel(const float* __restrict__ in2, const float* __restrict__ W,
                                const float* __restrict__ bias,
                                const float* __restrict__ Wdense, const float* __restrict__ opw,
                                const float* __restrict__ opb, const float* __restrict__ Wfuse) {
    if (blockIdx.x < QKV_BLOCKS) {
        int idx = blockIdx.x * 256 + threadIdx.x;
        int m = idx / (3 * P);
        int n = idx % (3 * P);
        const float4* x = (const float4*)(in2 + (size_t)m * P);
        const float4* wv = (const float4*)(W + (size_t)n * P);
        float acc = bias[n];
#pragma unroll
        for (int k = 0; k < 8; k++) {
            float4 a = __ldg(x + k), b = __ldg(wv + k);
            acc = fmaf(a.x, b.x, acc); acc = fmaf(a.y, b.y, acc);
            acc = fmaf(a.z, b.z, acc); acc = fmaf(a.w, b.w, acc);
        }
        g_qkv[idx] = acc;
    } else {
        int tid = threadIdx.x;
        for (int i = tid; i < 2 * H * T; i += 256) {
            int t = i >> 7, j = i & 127;
            float s = 0.f;
#pragma unroll
            for (int u = 0; u < T; u++) s = fmaf(Wdense[j * T + u], Wfuse[u * T + t], s);
            g_weff1T[t * 2 * H + j] = s;
        }
        for (int i = tid; i < P * T; i += 256) {
            int t = i >> 5, d = i & 31;
            float s = 0.f;
#pragma unroll
            for (int p = 0; p < P; p++) s = fmaf(opw[p * P + d], Wfuse[(T + p) * T + t], s);
            g_weff2T[t * P + d] = s;
        }
        if (tid < T) {
            float s = 0.f;
#pragma unroll
            for (int p = 0; p < P; p++) s = fmaf(opb[p], Wfuse[(T + p) * T + tid], s);
            g_beff[tid] = s;
        }
    }
}

// =================================================================
// K3: bi-GRU, one block per (batch, dir), 192 threads
// =================================================================
__global__ void __launch_bounds__(192) gru_kernel(
    const float* __restrict__ Whh_f, const float* __restrict__ Whh_b,
    const float* __restrict__ bhh_f, const float* __restrict__ bhh_b)
{
    __shared__ float hsh[H];
    __shared__ float ghsh[G];
    const int tid = threadIdx.x;
    const int b = blockIdx.x >> 1;
    const int dir = blockIdx.x & 1;

    float wreg[64];
    {
        const float* Whh = dir ? Whh_b : Whh_f;
        const float4* wr = (const float4*)(Whh + (size_t)tid * H);
#pragma unroll
        for (int i = 0; i < 16; i++) {
            float4 v = __ldg(wr + i);
            wreg[4 * i] = v.x; wreg[4 * i + 1] = v.y;
            wreg[4 * i + 2] = v.z; wreg[4 * i + 3] = v.w;
        }
    }
    const float bias = (dir ? bhh_b : bhh_f)[tid];
    if (tid < H) hsh[tid] = 0.f;
    __syncthreads();

    const float* xp = (dir ? g_xp_b : g_xp_f) + (size_t)b * S * G;
    float xr = 0.f, xz = 0.f, xn = 0.f;
    if (tid < H) {
        const float* xrow = xp + (size_t)(dir ? (S - 1) : 0) * G;
        xr = xrow[tid]; xz = xrow[H + tid]; xn = xrow[2 * H + tid];
    }
    for (int t = 0; t < S; t++) {
        const int te = dir ? (S - 1 - t) : t;
        {
            float a0 = bias, a1 = 0.f, a2 = 0.f, a3 = 0.f;
            const float4* hv = (const float4*)hsh;
#pragma unroll
            for (int i = 0; i < 16; i++) {
                float4 h4 = hv[i];
                a0 = fmaf(wreg[4 * i], h4.x, a0);
                a1 = fmaf(wreg[4 * i + 1], h4.y, a1);
                a2 = fmaf(wreg[4 * i + 2], h4.z, a2);
                a3 = fmaf(wreg[4 * i + 3], h4.w, a3);
            }
            ghsh[tid] = (a0 + a1) + (a2 + a3);
        }
        __syncthreads();
        float nxr = 0.f, nxz = 0.f, nxn = 0.f;
        if (t < S - 1 && tid < H) {
            const float* xrow = xp + (size_t)(dir ? (S - 2 - t) : (t + 1)) * G;
            nxr = xrow[tid]; nxz = xrow[H + tid]; nxn = xrow[2 * H + tid];
        }
        if (tid < H) {
            float r = sigmoidf_(xr + ghsh[tid]);
            float z = sigmoidf_(xz + ghsh[H + tid]);
            float nw = tanh_fast(xn + r * ghsh[2 * H + tid]);
            float hn = (1.f - z) * nw + z * hsh[tid];
            hsh[tid] = hn;
            g_lstm[((size_t)b * S + te) * (2 * H) + dir * H + tid] = hn;
        }
        __syncthreads();
        xr = nxr; xz = nxz; xn = nxn;
    }
}

// ---------------- K4: emissions ----------------
__global__ void __launch_bounds__(256) emis_kernel() {
    __shared__ float lrow[16 * 2 * H];
    __shared__ float arow[16 * P];
    __shared__ float w1s[T * 132];
    __shared__ float w2s[T * 36];
    __shared__ float bes[T];
    const int tid = threadIdx.x;
    const int r0 = blockIdx.x * 16;

    for (int i = tid; i < 16 * 2 * H; i += 256) lrow[i] = g_lstm[(size_t)r0 * 2 * H + i];
    for (int i = tid; i < 16 * P; i += 256) arow[i] = g_av[(size_t)r0 * P + i];
    for (int i = tid; i < T * 2 * H; i += 256) {
        int t = i >> 7, j = i & 127;
        w1s[t * 132 + j] = g_weff1T[i];
    }
    for (int i = tid; i < T * P; i += 256) {
        int t = i >> 5, d = i & 31;
        w2s[t * 36 + d] = g_weff2T[i];
    }
    if (tid < T) bes[tid] = g_beff[tid];
    __syncthreads();

    const int rr = tid >> 4;
    const int t = tid & 15;
    float acc = bes[t];
    const float4* lr = (const float4*)(lrow + rr * 2 * H);
    const float4* w1 = (const float4*)(w1s + t * 132);
#pragma unroll
    for (int i = 0; i < 32; i++) {
        float4 a = lr[i], wv = w1[i];
        acc = fmaf(a.x, wv.x, acc); acc = fmaf(a.y, wv.y, acc);
        acc = fmaf(a.z, wv.z, acc); acc = fmaf(a.w, wv.w, acc);
    }
    const float4* ar = (const float4*)(arow + rr * P);
    const float4* w2 = (const float4*)(w2s + t * 36);
#pragma unroll
    for (int i = 0; i < 8; i++) {
        float4 a = ar[i], wv = w2[i];
        acc = fmaf(a.x, wv.x, acc); acc = fmaf(a.y, wv.y, acc);
        acc = fmaf(a.z, wv.z, acc); acc = fmaf(a.w, wv.w, acc);
    }
    g_emis[(size_t)(r0 + rr) * T + t] = acc;
}

// ---------------- K5: CRF per batch (one warp) ----------------
__global__ void crf_kernel(const int* __restrict__ targets, const float* __restrict__ crf_start,
                           const float* __restrict__ crf_end, const float* __restrict__ crf_trans) {
    __shared__ float tr[T * 17];
    __shared__ float sc[T];
    __shared__ float st[T];
    __shared__ float en[T];
    __shared__ float s_num;
    const int b = blockIdx.x;
    const int lane = threadIdx.x;
    const int j = lane & 15, half = lane >> 4;

    for (int i = lane; i < T * T; i += 32) tr[(i >> 4) * 17 + (i & 15)] = crf_trans[i];
    if (lane < T) { st[lane] = crf_start[lane]; en[lane] = crf_end[lane]; }
    __syncthreads();

    const int* tg = targets + (size_t)b * S;
    float num = 0.f;
    for (int t = lane; t < S; t += 32) {
        int cur = tg[t];
        num += g_emis[((size_t)b * S + t) * T + cur];
        if (t < S - 1) num += tr[cur * 17 + tg[t + 1]];
    }
#pragma unroll
    for (int o = 16; o > 0; o >>= 1) num += __shfl_xor_sync(0xffffffffu, num, o);
    if (lane == 0) s_num = num + st[tg[0]] + en[tg[S - 1]];

    if (lane < T) sc[lane] = st[lane] + g_emis[((size_t)b * S) * T + lane];
    __syncwarp();
    __syncthreads();

    float em = g_emis[((size_t)b * S + 1) * T + j];
    for (int t = 1; t < S; t++) {
        float em_next = (t < S - 1) ? g_emis[((size_t)b * S + t + 1) * T + j] : 0.f;
        float x[8];
        float m = -1e30f;
#pragma unroll
        for (int i8 = 0; i8 < 8; i8++) {
            int i = half * 8 + i8;
            x[i8] = sc[i] + tr[i * 17 + j];
            m = fmaxf(m, x[i8]);
        }
        float ssum = 0.f;
#pragma unroll
        for (int i8 = 0; i8 < 8; i8++) ssum += __expf(x[i8] - m);
        float mo = __shfl_xor_sync(0xffffffffu, m, 16);
        float so = __shfl_xor_sync(0xffffffffu, ssum, 16);
        float m2 = fmaxf(m, mo);
        float stot = ssum * __expf(m - m2) + so * __expf(mo - m2);
        float nv = m2 + __logf(stot) + em;
        __syncwarp();
        if (half == 0) sc[j] = nv;
        __syncwarp();
        em = em_next;
    }

    float v = (lane < T) ? (sc[lane] + en[lane]) : -1e30f;
    float m = v;
#pragma unroll
    for (int o = 16; o > 0; o >>= 1) m = fmaxf(m, __shfl_xor_sync(0xffffffffu, m, o));
    float e = (lane < T) ? __expf(v - m) : 0.f;
#pragma unroll
    for (int o = 16; o > 0; o >>= 1) e += __shfl_xor_sync(0xffffffffu, e, o);
    __syncthreads();
    if (lane == 0) g_nll[b] = (m + __logf(e)) - s_num;
}

// ---------------- K6: final mean ----------------
__global__ void final_kernel(float* __restrict__ out) {
    __shared__ float red[B];
    red[threadIdx.x] = g_nll[threadIdx.x];
    __syncthreads();
    for (int stp = 32; stp > 0; stp >>= 1) {
        if (threadIdx.x < stp) red[threadIdx.x] += red[threadIdx.x + stp];
        __syncthreads();
    }
    if (threadIdx.x == 0) out[0] = red[0] * (1.0f / B);
}

// ---------------- launch ----------------
extern "C" void kernel_launch(void* const* d_in, const int* in_sizes, int n_in,
                              void* d_out, int out_size) {
    const float* bert = (const float*)d_in[0];
    const float* input2 = (const float*)d_in[1];
    const int* targets = (const int*)d_in[2];
    const float* Wih_f = (const float*)d_in[3];
    const float* Whh_f = (const float*)d_in[4];
    const float* bih_f = (const float*)d_in[5];
    const float* bhh_f = (const float*)d_in[6];
    const float* Wih_b = (const float*)d_in[7];
    const float* Whh_b = (const float*)d_in[8];
    const float* bih_b = (const float*)d_in[9];
    const float* bhh_b = (const float*)d_in[10];
    const float* Wdense = (const float*)d_in[11];
    const float* in_proj_w = (const float*)d_in[12];
    const float* in_proj_b = (const float*)d_in[13];
    const float* out_proj_w = (const float*)d_in[14];
    const float* out_proj_b = (const float*)d_in[15];
    const float* Wfuse = (const float*)d_in[16];
    const float* crf_start = (const float*)d_in[17];
    const float* crf_end = (const float*)d_in[18];
    const float* crf_trans = (const float*)d_in[19];
    float* out = (float*)d_out;

    cudaFuncSetAttribute(gemm_attn_kernel, cudaFuncAttributeMaxDynamicSharedMemorySize,
                         DSM_BYTES);

    // qkv (+weff as last block) — attention inputs ready before gemm+attn launch
    qkv_weff_kernel<<<QKV_BLOCKS + 1, 256>>>(input2, in_proj_w, in_proj_b,
                                             Wdense, out_proj_w, out_proj_b, Wfuse);
    // gemm (blocks 0..767) + attention (768..1279)
    gemm_attn_kernel<<<GEMM_BLOCKS + 512, 256, DSM_BYTES>>>(bert, Wih_f, Wih_b, bih_f, bih_b);
    // GRU alone (no issue-slot contention on its latency chain)
    gru_kernel<<<2 * B, 192>>>(Whh_f, Whh_b, bhh_f, bhh_b);
    // emissions
    emis_kernel<<<(B * S) / 16, 256>>>();
    // CRF
    crf_kernel<<<B, 32>>>(targets, crf_start, crf_end, crf_trans);
    // mean
    final_kernel<<<1, B>>>(out);
}

// round 4
// speedup vs baseline: 2.9500x; 1.1220x over previous
#include <cuda_runtime.h>
#include <cuda_bf16.h>
#include <math.h>
#include <stdint.h>

// Problem constants
#define B 64
#define S 512
#define E 768
#define H 64
#define G 192   // 3H
#define T 16
#define P 32

// ---------------- scratch ----------------
__device__ float g_xp_f[B * S * G];
__device__ float g_xp_b[B * S * G];
__device__ float g_lstm[B * S * 2 * H];
__device__ float g_qkv[B * S * 3 * P];
__device__ float g_av[B * S * P];
__device__ float g_emis[B * S * T];
__device__ float g_weff1T[T * 2 * H];
__device__ float g_weff2T[T * P];
__device__ float g_beff[T];
__device__ float g_nll[B];
__device__ int   g_flags[512 * 3];   // per (m_tile of 64 rows, n_tile of 128)

__device__ __forceinline__ float sigmoidf_(float x) { return 1.0f / (1.0f + __expf(-x)); }
__device__ __forceinline__ float tanh_fast(float x) {
    float y; asm("tanh.approx.f32 %0, %1;" : "=f"(y) : "f"(x)); return y;
}
__device__ __forceinline__ void cp16(uint32_t s, const void* g) {
    asm volatile("cp.async.cg.shared.global [%0], [%1], 16;\n" :: "r"(s), "l"(g));
}
__device__ __forceinline__ void cp_commit() { asm volatile("cp.async.commit_group;\n"); }
template <int N> __device__ __forceinline__ void cp_wait() {
    asm volatile("cp.async.wait_group %0;\n" :: "n"(N));
}

// =================================================================
// MEGA kernel: GRU (0..127) + GEMM (128..1663) + attention (1664..2175)
// GEMM: xp = bert @ [Wih_f;Wih_b]^T + bias, tf32 mma
//       BM=64, BN=128, BK=32, 3-stage cp.async, 8 warps, warp tile 16x64
// =================================================================
#define AST 36
#define STAGE_F (192 * AST)              // floats per stage (64 A rows + 128 B rows)
#define DSM_BYTES (3 * STAGE_F * 4)      // 82944
#define GRU_BLOCKS 128
#define GEMM_BLOCKS 1536
#define ATTN_OFF (GRU_BLOCKS + GEMM_BLOCKS)

__device__ __forceinline__ void poll2(int i0, int i1, int tid) {
    if (tid == 0) {
        volatile int* f = g_flags;
        while (f[i0] == 0) __nanosleep(64);
        while (f[i1] == 0) __nanosleep(64);
        __threadfence();
    }
    __syncthreads();
}

__global__ void __launch_bounds__(256, 2) mega_kernel(
    const float* __restrict__ A,
    const float* __restrict__ Wf, const float* __restrict__ Wb,
    const float* __restrict__ bf, const float* __restrict__ bb,
    const float* __restrict__ Whh_f, const float* __restrict__ Whh_b,
    const float* __restrict__ bhh_f, const float* __restrict__ bhh_b)
{
    extern __shared__ __align__(16) float dsm[];
    const int tid = threadIdx.x;

    if (blockIdx.x < GRU_BLOCKS) {
        // ---------------- GRU (consumer) ----------------
        const int b = blockIdx.x >> 1;
        const int dir = blockIdx.x & 1;
        float* hsh = dsm;
        float* ghsh = dsm + 64;
        const bool act = (tid < G);

        float wreg[64];
        float bias = 0.f;
        if (act) {
            const float* Whh = dir ? Whh_b : Whh_f;
            const float4* wr = (const float4*)(Whh + (size_t)tid * H);
#pragma unroll
            for (int i = 0; i < 16; i++) {
                float4 v = __ldg(wr + i);
                wreg[4 * i] = v.x; wreg[4 * i + 1] = v.y;
                wreg[4 * i + 2] = v.z; wreg[4 * i + 3] = v.w;
            }
            bias = (dir ? bhh_b : bhh_f)[tid];
        }
        if (tid < H) hsh[tid] = 0.f;

        const int te0 = dir ? (S - 1) : 0;
        {
            int c0 = te0 >> 6;
            int base = (b * 8 + c0) * 3;
            poll2(base + (dir ? 1 : 0), base + (dir ? 2 : 1), tid);  // includes __syncthreads
        }

        const float* xp = (dir ? g_xp_b : g_xp_f) + (size_t)b * S * G;
        float xr = 0.f, xz = 0.f, xn = 0.f;
        if (tid < H) {
            const float* xrow = xp + (size_t)te0 * G;
            xr = xrow[tid]; xz = xrow[H + tid]; xn = xrow[2 * H + tid];
        }
        for (int t = 0; t < S; t++) {
            const int te = dir ? (S - 1 - t) : t;
            if (act) {
                float a0 = bias, a1 = 0.f, a2 = 0.f, a3 = 0.f;
                const float4* hv = (const float4*)hsh;
#pragma unroll
                for (int i = 0; i < 16; i++) {
                    float4 h4 = hv[i];
                    a0 = fmaf(wreg[4 * i], h4.x, a0);
                    a1 = fmaf(wreg[4 * i + 1], h4.y, a1);
                    a2 = fmaf(wreg[4 * i + 2], h4.z, a2);
                    a3 = fmaf(wreg[4 * i + 3], h4.w, a3);
                }
                ghsh[tid] = (a0 + a1) + (a2 + a3);
            }
            __syncthreads();
            if (((t + 1) & 63) == 0 && (t + 1) < S) {
                int ten = dir ? (S - 2 - t) : (t + 1);
                int c = ten >> 6;
                int base = (b * 8 + c) * 3;
                poll2(base + (dir ? 1 : 0), base + (dir ? 2 : 1), tid);
            }
            float nxr = 0.f, nxz = 0.f, nxn = 0.f;
            if (t < S - 1 && tid < H) {
                const float* xrow = xp + (size_t)(dir ? (S - 2 - t) : (t + 1)) * G;
                nxr = xrow[tid]; nxz = xrow[H + tid]; nxn = xrow[2 * H + tid];
            }
            if (tid < H) {
                float r = sigmoidf_(xr + ghsh[tid]);
                float z = sigmoidf_(xz + ghsh[H + tid]);
                float nw = tanh_fast(xn + r * ghsh[2 * H + tid]);
                float hn = (1.f - z) * nw + z * hsh[tid];
                hsh[tid] = hn;
                g_lstm[((size_t)b * S + te) * (2 * H) + dir * H + tid] = hn;
            }
            __syncthreads();
            xr = nxr; xz = nxz; xn = nxn;
        }
    } else if (blockIdx.x < ATTN_OFF) {
        // ---------------- GEMM (producer) ----------------
        const int bid = blockIdx.x - GRU_BLOCKS;
        const int nidx = bid % 3;
        const int r = bid / 3;            // 0..511
        const int p = r >> 7;             // phase 0..3
        const int q = r & 127;
        const int batch = q & 63;
        const int which = q >> 6;
        const int chunk = which ? (7 - p) : p;
        const int m_tile = batch * 8 + chunk;   // 0..511
        const int bm = m_tile * 64;
        const int bn = nidx * 128;

        const int w = tid >> 5, lane = tid & 31;
        const int wm = (w >> 1) * 16;     // 0,16,32,48
        const int wn = (w & 1) * 64;      // 0,64
        const int grp = lane >> 2, tig = lane & 3;

        const uint32_t smb = (uint32_t)__cvta_generic_to_shared(dsm);

        // loader tasks
        // A: 512 float4 (64 rows x 8 c4) -> 2 per thread
        // B: 1024 float4 (128 rows x 8 c4) -> 4 per thread
        int arow[2], ac4[2];
        const float* aptr[2];
#pragma unroll
        for (int i = 0; i < 2; i++) {
            int idx = tid + 256 * i;
            arow[i] = idx >> 3; ac4[i] = idx & 7;
            aptr[i] = A + (size_t)(bm + arow[i]) * E + ac4[i] * 4;
        }
        int brow[4], bc4[4];
        const float* bptr[4];
#pragma unroll
        for (int i = 0; i < 4; i++) {
            int idx = tid + 256 * i;
            brow[i] = idx >> 3; bc4[i] = idx & 7;
            int nrow = bn + brow[i];
            bptr[i] = (nrow < G) ? (Wf + (size_t)nrow * E + bc4[i] * 4)
                                 : (Wb + (size_t)(nrow - G) * E + bc4[i] * 4);
        }

        float acc[8][4];
#pragma unroll
        for (int nt = 0; nt < 8; nt++)
#pragma unroll
            for (int d = 0; d < 4; d++) acc[nt][d] = 0.0f;

        // prologue: tiles 0 and 1
#pragma unroll
        for (int s = 0; s < 2; s++) {
            uint32_t sb = smb + s * STAGE_F * 4;
#pragma unroll
            for (int i = 0; i < 2; i++)
                cp16(sb + (arow[i] * AST + ac4[i] * 4) * 4, aptr[i] + s * 32);
#pragma unroll
            for (int i = 0; i < 4; i++)
                cp16(sb + ((64 + brow[i]) * AST + bc4[i] * 4) * 4, bptr[i] + s * 32);
            cp_commit();
        }

        for (int kt = 0; kt < 24; kt++) {
            if (kt < 22) cp_wait<1>(); else cp_wait<0>();
            __syncthreads();
            if (kt + 2 < 24) {
                const int st = (kt + 2) % 3;
                const int kn = (kt + 2) * 32;
                uint32_t sb = smb + st * STAGE_F * 4;
#pragma unroll
                for (int i = 0; i < 2; i++)
                    cp16(sb + (arow[i] * AST + ac4[i] * 4) * 4, aptr[i] + kn);
#pragma unroll
                for (int i = 0; i < 4; i++)
                    cp16(sb + ((64 + brow[i]) * AST + bc4[i] * 4) * 4, bptr[i] + kn);
                cp_commit();
            }
            const int s = kt % 3;
            const uint32_t* As = (const uint32_t*)(dsm + s * STAGE_F);
            const uint32_t* Bs = As + 64 * AST;
#pragma unroll
            for (int ks = 0; ks < 4; ks++) {
                const int ko = ks * 8;
                uint32_t afr[4];
                {
                    const uint32_t* pa = As + (wm + grp) * AST + ko + tig;
                    afr[0] = pa[0];
                    afr[2] = pa[4];
                    afr[1] = pa[8 * AST];
                    afr[3] = pa[8 * AST + 4];
                }
#pragma unroll
                for (int nt = 0; nt < 8; nt++) {
                    const uint32_t* pb = Bs + (wn + nt * 8 + grp) * AST + ko + tig;
                    uint32_t b0 = pb[0], b1 = pb[4];
                    asm volatile(
                        "mma.sync.aligned.m16n8k8.row.col.f32.tf32.tf32.f32 "
                        "{%0,%1,%2,%3},{%4,%5,%6,%7},{%8,%9},{%0,%1,%2,%3};"
                        : "+f"(acc[nt][0]), "+f"(acc[nt][1]),
                          "+f"(acc[nt][2]), "+f"(acc[nt][3])
                        : "r"(afr[0]), "r"(afr[1]), "r"(afr[2]), "r"(afr[3]),
                          "r"(b0), "r"(b1));
                }
            }
        }

        // epilogue
        {
            int m0 = bm + wm + grp;
#pragma unroll
            for (int nt = 0; nt < 8; nt++) {
                int n = bn + wn + nt * 8 + 2 * tig;
                float* dst; const float* bp; int nn;
                if (n < G) { dst = g_xp_f; bp = bf; nn = n; }
                else       { dst = g_xp_b; bp = bb; nn = n - G; }
                float b0 = __ldg(bp + nn), b1 = __ldg(bp + nn + 1);
                *(float2*)(dst + (size_t)m0 * G + nn) =
                    make_float2(acc[nt][0] + b0, acc[nt][1] + b1);
                *(float2*)(dst + (size_t)(m0 + 8) * G + nn) =
                    make_float2(acc[nt][2] + b0, acc[nt][3] + b1);
            }
        }
        __syncthreads();
        if (tid == 0) {
            __threadfence();
            atomicExch(&g_flags[m_tile * 3 + nidx], 1);
        }
    } else {
        // ---------------- flash attention ----------------
        const int bid = blockIdx.x - ATTN_OFF;
        const int qt = bid & 7, b = bid >> 3;
        float* Ks = dsm;                  // [64][36]
        float* Vs = dsm + 64 * 36;        // [64][36]
        float* psh = dsm + 2 * 64 * 36;   // [64][68]
        const int q = tid >> 2, kg = tid & 3;
        const int qg = qt * 64 + q;
        const float scale = 0.17677669529663689f;

        float4 qv[8];
        {
            const float4* qp = (const float4*)(g_qkv + ((size_t)b * S + qg) * (3 * P));
#pragma unroll
            for (int i = 0; i < 8; i++) qv[i] = __ldg(qp + i);
        }
        float av0[4] = {0.f, 0.f, 0.f, 0.f}, av1[4] = {0.f, 0.f, 0.f, 0.f};
        float mrun = -1e30f, lrun = 0.f;

        for (int kt = 0; kt < 8; kt++) {
            __syncthreads();
            for (int i = tid; i < 64 * P; i += 256) {
                int row = i >> 5, d = i & 31;
                const float* base = g_qkv + ((size_t)b * S + kt * 64 + row) * (3 * P);
                Ks[row * 36 + d] = base[P + d];
                Vs[row * 36 + d] = base[2 * P + d];
            }
            __syncthreads();

            float sv[16];
            float tmax = -1e30f;
#pragma unroll
            for (int kl = 0; kl < 16; kl++) {
                int k = kg + kl * 4;
                const float4* kr = (const float4*)(Ks + k * 36);
                float d0 = 0.f, d1 = 0.f, d2 = 0.f, d3 = 0.f;
#pragma unroll
                for (int i = 0; i < 8; i += 4) {
                    float4 k0 = kr[i], k1 = kr[i + 1], k2 = kr[i + 2], k3 = kr[i + 3];
                    d0 = fmaf(qv[i].x, k0.x, d0); d0 = fmaf(qv[i].y, k0.y, d0);
                    d0 = fmaf(qv[i].z, k0.z, d0); d0 = fmaf(qv[i].w, k0.w, d0);
                    d1 = fmaf(qv[i+1].x, k1.x, d1); d1 = fmaf(qv[i+1].y, k1.y, d1);
                    d1 = fmaf(qv[i+1].z, k1.z, d1); d1 = fmaf(qv[i+1].w, k1.w, d1);
                    d2 = fmaf(qv[i+2].x, k2.x, d2); d2 = fmaf(qv[i+2].y, k2.y, d2);
                    d2 = fmaf(qv[i+2].z, k2.z, d2); d2 = fmaf(qv[i+2].w, k2.w, d2);
                    d3 = fmaf(qv[i+3].x, k3.x, d3); d3 = fmaf(qv[i+3].y, k3.y, d3);
                    d3 = fmaf(qv[i+3].z, k3.z, d3); d3 = fmaf(qv[i+3].w, k3.w, d3);
                }
                sv[kl] = ((d0 + d1) + (d2 + d3)) * scale;
                tmax = fmaxf(tmax, sv[kl]);
            }
            tmax = fmaxf(tmax, __shfl_xor_sync(0xffffffffu, tmax, 1));
            tmax = fmaxf(tmax, __shfl_xor_sync(0xffffffffu, tmax, 2));
            float mnew = fmaxf(mrun, tmax);
            float corr = __expf(mrun - mnew);
            float tsum = 0.f;
#pragma unroll
            for (int kl = 0; kl < 16; kl++) {
                float e = __expf(sv[kl] - mnew);
                psh[q * 68 + kg + kl * 4] = e;
                tsum += e;
            }
            tsum += __shfl_xor_sync(0xffffffffu, tsum, 1);
            tsum += __shfl_xor_sync(0xffffffffu, tsum, 2);
            lrun = lrun * corr + tsum;
            mrun = mnew;
#pragma unroll
            for (int j = 0; j < 4; j++) { av0[j] *= corr; av1[j] *= corr; }
            __syncwarp();
#pragma unroll 4
            for (int k = 0; k < 64; k++) {
                float pv = psh[q * 68 + k];
                const float4* vr = (const float4*)(Vs + k * 36 + kg * 8);
                float4 v0 = vr[0], v1 = vr[1];
                av0[0] = fmaf(pv, v0.x, av0[0]); av0[1] = fmaf(pv, v0.y, av0[1]);
                av0[2] = fmaf(pv, v0.z, av0[2]); av0[3] = fmaf(pv, v0.w, av0[3]);
                av1[0] = fmaf(pv, v1.x, av1[0]); av1[1] = fmaf(pv, v1.y, av1[1]);
                av1[2] = fmaf(pv, v1.z, av1[2]); av1[3] = fmaf(pv, v1.w, av1[3]);
            }
            __syncwarp();
        }
        float inv = 1.0f / lrun;
        float* op = g_av + ((size_t)b * S + qg) * P + kg * 8;
        *(float4*)(op) = make_float4(av0[0] * inv, av0[1] * inv, av0[2] * inv, av0[3] * inv);
        *(float4*)(op + 4) = make_float4(av1[0] * inv, av1[1] * inv, av1[2] * inv, av1[3] * inv);
    }
}

// =================================================================
// K1: qkv + folded weights + flag reset
// =================================================================
#define QKV_BLOCKS ((B * S * 3 * P) / 256)
__global__ void qkv_weff_kernel(const float* __restrict__ in2, const float* __restrict__ W,
                                const float* __restrict__ bias,
                                const float* __restrict__ Wdense, const float* __restrict__ opw,
                                const float* __restrict__ opb, const float* __restrict__ Wfuse) {
    if (blockIdx.x < QKV_BLOCKS) {
        int idx = blockIdx.x * 256 + threadIdx.x;
        int m = idx / (3 * P);
        int n = idx % (3 * P);
        const float4* x = (const float4*)(in2 + (size_t)m * P);
        const float4* wv = (const float4*)(W + (size_t)n * P);
        float acc = bias[n];
#pragma unroll
        for (int k = 0; k < 8; k++) {
            float4 a = __ldg(x + k), b = __ldg(wv + k);
            acc = fmaf(a.x, b.x, acc); acc = fmaf(a.y, b.y, acc);
            acc = fmaf(a.z, b.z, acc); acc = fmaf(a.w, b.w, acc);
        }
        g_qkv[idx] = acc;
    } else {
        int tid = threadIdx.x;
        for (int i = tid; i < 512 * 3; i += 256) g_flags[i] = 0;
        for (int i = tid; i < 2 * H * T; i += 256) {
            int t = i >> 7, j = i & 127;
            float s = 0.f;
#pragma unroll
            for (int u = 0; u < T; u++) s = fmaf(Wdense[j * T + u], Wfuse[u * T + t], s);
            g_weff1T[t * 2 * H + j] = s;
        }
        for (int i = tid; i < P * T; i += 256) {
            int t = i >> 5, d = i & 31;
            float s = 0.f;
#pragma unroll
            for (int p = 0; p < P; p++) s = fmaf(opw[p * P + d], Wfuse[(T + p) * T + t], s);
            g_weff2T[t * P + d] = s;
        }
        if (tid < T) {
            float s = 0.f;
#pragma unroll
            for (int p = 0; p < P; p++) s = fmaf(opb[p], Wfuse[(T + p) * T + tid], s);
            g_beff[tid] = s;
        }
        __threadfence();
    }
}

// ---------------- emissions ----------------
__global__ void __launch_bounds__(256) emis_kernel() {
    __shared__ float lrow[16 * 2 * H];
    __shared__ float arow[16 * P];
    __shared__ float w1s[T * 133];
    __shared__ float w2s[T * 37];
    __shared__ float bes[T];
    const int tid = threadIdx.x;
    const int r0 = blockIdx.x * 16;

    for (int i = tid; i < 16 * 2 * H; i += 256) lrow[i] = g_lstm[(size_t)r0 * 2 * H + i];
    for (int i = tid; i < 16 * P; i += 256) arow[i] = g_av[(size_t)r0 * P + i];
    for (int i = tid; i < T * 2 * H; i += 256) {
        int t = i >> 7, j = i & 127;
        w1s[t * 133 + j] = g_weff1T[i];
    }
    for (int i = tid; i < T * P; i += 256) {
        int t = i >> 5, d = i & 31;
        w2s[t * 37 + d] = g_weff2T[i];
    }
    if (tid < T) bes[tid] = g_beff[tid];
    __syncthreads();

    const int rr = tid >> 4;
    const int t = tid & 15;
    float acc = bes[t];
    const float* lr = lrow + rr * 2 * H;
    const float* w1 = w1s + t * 133;
#pragma unroll
    for (int i = 0; i < 2 * H; i += 4) {
        acc = fmaf(lr[i], w1[i], acc);
        acc = fmaf(lr[i + 1], w1[i + 1], acc);
        acc = fmaf(lr[i + 2], w1[i + 2], acc);
        acc = fmaf(lr[i + 3], w1[i + 3], acc);
    }
    const float* ar = arow + rr * P;
    const float* w2 = w2s + t * 37;
#pragma unroll
    for (int i = 0; i < P; i += 4) {
        acc = fmaf(ar[i], w2[i], acc);
        acc = fmaf(ar[i + 1], w2[i + 1], acc);
        acc = fmaf(ar[i + 2], w2[i + 2], acc);
        acc = fmaf(ar[i + 3], w2[i + 3], acc);
    }
    g_emis[(size_t)(r0 + rr) * T + t] = acc;
}

// ---------------- CRF per batch (one warp) ----------------
// exp(sc_i + tr_ij) = exp(sc_i - anchor) * E_ij, E precomputed in regs
__global__ void crf_kernel(const int* __restrict__ targets, const float* __restrict__ crf_start,
                           const float* __restrict__ crf_end, const float* __restrict__ crf_trans) {
    __shared__ float tr[T * 17];
    __shared__ float sc[T];
    __shared__ float st[T];
    __shared__ float en[T];
    __shared__ float s_num;
    const int b = blockIdx.x;
    const int lane = threadIdx.x;
    const int j = lane & 15, half = lane >> 4;

    for (int i = lane; i < T * T; i += 32) tr[(i >> 4) * 17 + (i & 15)] = crf_trans[i];
    if (lane < T) { st[lane] = crf_start[lane]; en[lane] = crf_end[lane]; }
    __syncthreads();

    // E_kj for k in half*8..half*8+7
    float Ereg[8];
#pragma unroll
    for (int k = 0; k < 8; k++) Ereg[k] = __expf(tr[(half * 8 + k) * 17 + j]);

    // numerator
    const int* tg = targets + (size_t)b * S;
    float num = 0.f;
    for (int t = lane; t < S; t += 32) {
        int cur = tg[t];
        num += g_emis[((size_t)b * S + t) * T + cur];
        if (t < S - 1) num += tr[cur * 17 + tg[t + 1]];
    }
#pragma unroll
    for (int o = 16; o > 0; o >>= 1) num += __shfl_xor_sync(0xffffffffu, num, o);
    if (lane == 0) s_num = num + st[tg[0]] + en[tg[S - 1]];

    if (lane < T) sc[lane] = st[lane] + g_emis[((size_t)b * S) * T + lane];
    __syncwarp();

    float em = g_emis[((size_t)b * S + 1) * T + j];
    for (int t = 1; t < S; t++) {
        float em_next = (t < S - 1) ? g_emis[((size_t)b * S + t + 1) * T + j] : 0.f;
        float anchor = sc[0];
        float myе_src = sc[j];
        float mye = __expf(myе_src - anchor);
        float acc = 0.f;
#pragma unroll
        for (int k = 0; k < 8; k++) {
            float ek = __shfl_sync(0xffffffffu, mye, half * 8 + k);
            acc = fmaf(ek, Ereg[k], acc);
        }
        acc += __shfl_xor_sync(0xffffffffu, acc, 16);
        float nxt = anchor + __logf(acc) + em;
        // all lanes have passed their sc reads (shfl barriers above) — safe to overwrite
        if (lane < T) sc[lane] = nxt;
        __syncwarp();
        em = em_next;
    }

    float v = (lane < T) ? (sc[lane] + en[lane]) : -1e30f;
    float m = v;
#pragma unroll
    for (int o = 16; o > 0; o >>= 1) m = fmaxf(m, __shfl_xor_sync(0xffffffffu, m, o));
    float e = (lane < T) ? __expf(v - m) : 0.f;
#pragma unroll
    for (int o = 16; o > 0; o >>= 1) e += __shfl_xor_sync(0xffffffffu, e, o);
    __syncthreads();
    if (lane == 0) g_nll[b] = (m + __logf(e)) - s_num;
}

// ---------------- final mean ----------------
__global__ void final_kernel(float* __restrict__ out) {
    __shared__ float red[B];
    red[threadIdx.x] = g_nll[threadIdx.x];
    __syncthreads();
    for (int stp = 32; stp > 0; stp >>= 1) {
        if (threadIdx.x < stp) red[threadIdx.x] += red[threadIdx.x + stp];
        __syncthreads();
    }
    if (threadIdx.x == 0) out[0] = red[0] * (1.0f / B);
}

// ---------------- launch ----------------
extern "C" void kernel_launch(void* const* d_in, const int* in_sizes, int n_in,
                              void* d_out, int out_size) {
    const float* bert = (const float*)d_in[0];
    const float* input2 = (const float*)d_in[1];
    const int* targets = (const int*)d_in[2];
    const float* Wih_f = (const float*)d_in[3];
    const float* Whh_f = (const float*)d_in[4];
    const float* bih_f = (const float*)d_in[5];
    const float* bhh_f = (const float*)d_in[6];
    const float* Wih_b = (const float*)d_in[7];
    const float* Whh_b = (const float*)d_in[8];
    const float* bih_b = (const float*)d_in[9];
    const float* bhh_b = (const float*)d_in[10];
    const float* Wdense = (const float*)d_in[11];
    const float* in_proj_w = (const float*)d_in[12];
    const float* in_proj_b = (const float*)d_in[13];
    const float* out_proj_w = (const float*)d_in[14];
    const float* out_proj_b = (const float*)d_in[15];
    const float* Wfuse = (const float*)d_in[16];
    const float* crf_start = (const float*)d_in[17];
    const float* crf_end = (const float*)d_in[18];
    const float* crf_trans = (const float*)d_in[19];
    float* out = (float*)d_out;

    cudaFuncSetAttribute(mega_kernel, cudaFuncAttributeMaxDynamicSharedMemorySize, DSM_BYTES);

    // qkv (+weff + flag reset)
    qkv_weff_kernel<<<QKV_BLOCKS + 1, 256>>>(input2, in_proj_w, in_proj_b,
                                             Wdense, out_proj_w, out_proj_b, Wfuse);
    // GRU (0..127) + GEMM (128..1663) + attention (1664..2175)
    mega_kernel<<<ATTN_OFF + 512, 256, DSM_BYTES>>>(bert, Wih_f, Wih_b, bih_f, bih_b,
                                                    Whh_f, Whh_b, bhh_f, bhh_b);
    // emissions
    emis_kernel<<<(B * S) / 16, 256>>>();
    // CRF
    crf_kernel<<<B, 32>>>(targets, crf_start, crf_end, crf_trans);
    // mean
    final_kernel<<<1, B>>>(out);
}

// round 5
// speedup vs baseline: 3.2228x; 1.0925x over previous
#include <cuda_runtime.h>
#include <cuda_bf16.h>
#include <math.h>
#include <stdint.h>

// Problem constants
#define B 64
#define S 512
#define E 768
#define H 64
#define G 192   // 3H
#define T 16
#define P 32

// ---------------- scratch ----------------
__device__ float g_xp_f[B * S * G];
__device__ float g_xp_b[B * S * G];
__device__ float g_lstm[B * S * 2 * H];
__device__ float g_qkv[B * S * 3 * P];
__device__ float g_av[B * S * P];
__device__ float g_emis[B * S * T];
__device__ float g_weff1T[T * 2 * H];
__device__ float g_weff2T[T * P];
__device__ float g_beff[T];
__device__ float g_nll[B];
__device__ int   g_flags[256 * 3];                 // (m_tile of 128 rows, n_tile of 128)
__device__ __nv_bfloat16 g_bert_h[B * S * E];      // 50 MB
__device__ __nv_bfloat16 g_wh[2 * G * E];          // [384][768] combined Wih_f;Wih_b

__device__ __forceinline__ float sigmoidf_(float x) { return 1.0f / (1.0f + __expf(-x)); }
__device__ __forceinline__ float tanh_fast(float x) {
    float y; asm("tanh.approx.f32 %0, %1;" : "=f"(y) : "f"(x)); return y;
}
__device__ __forceinline__ void cp16(uint32_t s, const void* g) {
    asm volatile("cp.async.cg.shared.global [%0], [%1], 16;\n" :: "r"(s), "l"(g));
}
__device__ __forceinline__ void cp_commit() { asm volatile("cp.async.commit_group;\n"); }
template <int N> __device__ __forceinline__ void cp_wait() {
    asm volatile("cp.async.wait_group %0;\n" :: "n"(N));
}

// =================================================================
// MEGA: GRU (0..127) + bf16 GEMM (128..895) + attention (896..1407)
// GEMM: xp = bert @ [Wih_f;Wih_b]^T + bias, bf16 mma m16n8k16
//       BM=128, BN=128, BK=32, 3-stage cp.async, 8 warps, warp 64x32
// =================================================================
#define KST 20                         // smem row stride in u32 (32 bf16 + pad)
#define STAGE_U (2 * 128 * KST)        // 5120 u32 per stage
#define DSM_BYTES (3 * STAGE_U * 4)    // 61440
#define GRU_BLOCKS 128
#define GEMM_BLOCKS 768
#define ATTN_OFF (GRU_BLOCKS + GEMM_BLOCKS)

__device__ __forceinline__ void poll2(int i0, int i1, int tid) {
    if (tid == 0) {
        volatile int* f = g_flags;
        while (f[i0] == 0) __nanosleep(64);
        while (f[i1] == 0) __nanosleep(64);
        __threadfence();
    }
    __syncthreads();
}

__global__ void __launch_bounds__(256, 2) mega_kernel(
    const float* __restrict__ bf, const float* __restrict__ bb,
    const float* __restrict__ Whh_f, const float* __restrict__ Whh_b,
    const float* __restrict__ bhh_f, const float* __restrict__ bhh_b)
{
    extern __shared__ __align__(16) float dsm[];
    const int tid = threadIdx.x;

    if (blockIdx.x < GRU_BLOCKS) {
        // ---------------- GRU (consumer) ----------------
        const int b = blockIdx.x >> 1;
        const int dir = blockIdx.x & 1;
        float* hsh = dsm;
        float* ghsh = dsm + 64;
        const bool act = (tid < G);

        float wreg[64];
        float bias = 0.f;
        if (act) {
            const float* Whh = dir ? Whh_b : Whh_f;
            const float4* wr = (const float4*)(Whh + (size_t)tid * H);
#pragma unroll
            for (int i = 0; i < 16; i++) {
                float4 v = __ldg(wr + i);
                wreg[4 * i] = v.x; wreg[4 * i + 1] = v.y;
                wreg[4 * i + 2] = v.z; wreg[4 * i + 3] = v.w;
            }
            bias = (dir ? bhh_b : bhh_f)[tid];
        }
        if (tid < H) hsh[tid] = 0.f;

        const int te0 = dir ? (S - 1) : 0;
        {
            int c0 = te0 >> 7;
            int base = (b * 4 + c0) * 3;
            poll2(base + (dir ? 1 : 0), base + (dir ? 2 : 1), tid);
        }

        const float* xp = (dir ? g_xp_b : g_xp_f) + (size_t)b * S * G;
        float xr = 0.f, xz = 0.f, xn = 0.f;
        if (tid < H) {
            const float* xrow = xp + (size_t)te0 * G;
            xr = xrow[tid]; xz = xrow[H + tid]; xn = xrow[2 * H + tid];
        }
        for (int t = 0; t < S; t++) {
            const int te = dir ? (S - 1 - t) : t;
            if (act) {
                float a0 = bias, a1 = 0.f, a2 = 0.f, a3 = 0.f;
                const float4* hv = (const float4*)hsh;
#pragma unroll
                for (int i = 0; i < 16; i++) {
                    float4 h4 = hv[i];
                    a0 = fmaf(wreg[4 * i], h4.x, a0);
                    a1 = fmaf(wreg[4 * i + 1], h4.y, a1);
                    a2 = fmaf(wreg[4 * i + 2], h4.z, a2);
                    a3 = fmaf(wreg[4 * i + 3], h4.w, a3);
                }
                ghsh[tid] = (a0 + a1) + (a2 + a3);
            }
            __syncthreads();
            if (((t + 1) & 127) == 0 && (t + 1) < S) {
                int ten = dir ? (S - 2 - t) : (t + 1);
                int c = ten >> 7;
                int base = (b * 4 + c) * 3;
                poll2(base + (dir ? 1 : 0), base + (dir ? 2 : 1), tid);
            }
            float nxr = 0.f, nxz = 0.f, nxn = 0.f;
            if (t < S - 1 && tid < H) {
                const float* xrow = xp + (size_t)(dir ? (S - 2 - t) : (t + 1)) * G;
                nxr = xrow[tid]; nxz = xrow[H + tid]; nxn = xrow[2 * H + tid];
            }
            if (tid < H) {
                float r = sigmoidf_(xr + ghsh[tid]);
                float z = sigmoidf_(xz + ghsh[H + tid]);
                float nw = tanh_fast(xn + r * ghsh[2 * H + tid]);
                float hn = (1.f - z) * nw + z * hsh[tid];
                hsh[tid] = hn;
                g_lstm[((size_t)b * S + te) * (2 * H) + dir * H + tid] = hn;
            }
            __syncthreads();
            xr = nxr; xz = nxz; xn = nxn;
        }
    } else if (blockIdx.x < ATTN_OFF) {
        // ---------------- bf16 GEMM (producer) ----------------
        const int bid = blockIdx.x - GRU_BLOCKS;
        const int nidx = bid % 3;
        const int r = bid / 3;            // 0..255
        const int p = r >> 7;             // phase 0..1
        const int q = r & 127;
        const int batch = q & 63;
        const int which = q >> 6;
        const int chunk = which ? (3 - p) : p;
        const int m_tile = batch * 4 + chunk;   // 0..255
        const int bm = m_tile * 128;
        const int bn = nidx * 128;

        const int w = tid >> 5, lane = tid & 31;
        const int wm = (w >> 2) * 64, wn = (w & 3) * 32;
        const int grp = lane >> 2, tig = lane & 3;

        const uint32_t smb = (uint32_t)__cvta_generic_to_shared(dsm);

        // loaders: A 512 x 16B tasks, B 512 x 16B tasks -> 2+2 per thread
        int lrow[2], lc[2];
        const __nv_bfloat16* aptr[2];
        const __nv_bfloat16* bptr[2];
#pragma unroll
        for (int i = 0; i < 2; i++) {
            int task = tid + 256 * i;
            lrow[i] = task >> 2; lc[i] = task & 3;
            aptr[i] = g_bert_h + (size_t)(bm + lrow[i]) * E + lc[i] * 8;
            bptr[i] = g_wh + (size_t)(bn + lrow[i]) * E + lc[i] * 8;
        }

        float acc[4][4][4];
#pragma unroll
        for (int mt = 0; mt < 4; mt++)
#pragma unroll
            for (int nt = 0; nt < 4; nt++)
#pragma unroll
                for (int d = 0; d < 4; d++) acc[mt][nt][d] = 0.0f;

        // prologue: tiles 0,1
#pragma unroll
        for (int s = 0; s < 2; s++) {
            uint32_t sb = smb + s * STAGE_U * 4;
#pragma unroll
            for (int i = 0; i < 2; i++) {
                cp16(sb + (lrow[i] * KST + lc[i] * 4) * 4, aptr[i] + s * 32);
                cp16(sb + ((128 + lrow[i]) * KST + lc[i] * 4) * 4, bptr[i] + s * 32);
            }
            cp_commit();
        }

        for (int kt = 0; kt < 24; kt++) {
            if (kt < 22) cp_wait<1>(); else cp_wait<0>();
            __syncthreads();
            if (kt + 2 < 24) {
                const int st = (kt + 2) % 3;
                const int kn = (kt + 2) * 32;
                uint32_t sb = smb + st * STAGE_U * 4;
#pragma unroll
                for (int i = 0; i < 2; i++) {
                    cp16(sb + (lrow[i] * KST + lc[i] * 4) * 4, aptr[i] + kn);
                    cp16(sb + ((128 + lrow[i]) * KST + lc[i] * 4) * 4, bptr[i] + kn);
                }
                cp_commit();
            }
            const int s = kt % 3;
            const uint32_t* As = (const uint32_t*)dsm + s * STAGE_U;
            const uint32_t* Bs = As + 128 * KST;
#pragma unroll
            for (int ks = 0; ks < 2; ks++) {
                const int ko = ks * 8;
                uint32_t afr[4][4], bfr[4][2];
#pragma unroll
                for (int mt = 0; mt < 4; mt++) {
                    const uint32_t* pa = As + (wm + mt * 16 + grp) * KST + ko + tig;
                    afr[mt][0] = pa[0];
                    afr[mt][1] = pa[8 * KST];
                    afr[mt][2] = pa[4];
                    afr[mt][3] = pa[8 * KST + 4];
                }
#pragma unroll
                for (int nt = 0; nt < 4; nt++) {
                    const uint32_t* pb = Bs + (wn + nt * 8 + grp) * KST + ko + tig;
                    bfr[nt][0] = pb[0];
                    bfr[nt][1] = pb[4];
                }
#pragma unroll
                for (int mt = 0; mt < 4; mt++)
#pragma unroll
                    for (int nt = 0; nt < 4; nt++) {
                        asm volatile(
                            "mma.sync.aligned.m16n8k16.row.col.f32.bf16.bf16.f32 "
                            "{%0,%1,%2,%3},{%4,%5,%6,%7},{%8,%9},{%0,%1,%2,%3};"
                            : "+f"(acc[mt][nt][0]), "+f"(acc[mt][nt][1]),
                              "+f"(acc[mt][nt][2]), "+f"(acc[mt][nt][3])
                            : "r"(afr[mt][0]), "r"(afr[mt][1]), "r"(afr[mt][2]), "r"(afr[mt][3]),
                              "r"(bfr[nt][0]), "r"(bfr[nt][1]));
                    }
            }
        }

        // epilogue
#pragma unroll
        for (int mt = 0; mt < 4; mt++) {
            int m0 = bm + wm + mt * 16 + grp;
#pragma unroll
            for (int nt = 0; nt < 4; nt++) {
                int n = bn + wn + nt * 8 + 2 * tig;
                float* dst; const float* bp; int nn;
                if (n < G) { dst = g_xp_f; bp = bf; nn = n; }
                else       { dst = g_xp_b; bp = bb; nn = n - G; }
                float b0 = __ldg(bp + nn), b1 = __ldg(bp + nn + 1);
                *(float2*)(dst + (size_t)m0 * G + nn) =
                    make_float2(acc[mt][nt][0] + b0, acc[mt][nt][1] + b1);
                *(float2*)(dst + (size_t)(m0 + 8) * G + nn) =
                    make_float2(acc[mt][nt][2] + b0, acc[mt][nt][3] + b1);
            }
        }
        __syncthreads();
        if (tid == 0) {
            __threadfence();
            atomicExch(&g_flags[m_tile * 3 + nidx], 1);
        }
    } else {
        // ---------------- flash attention ----------------
        const int bid = blockIdx.x - ATTN_OFF;
        const int qt = bid & 7, b = bid >> 3;
        float* Ks = dsm;
        float* Vs = dsm + 64 * 36;
        float* psh = dsm + 2 * 64 * 36;
        const int q = tid >> 2, kg = tid & 3;
        const int qg = qt * 64 + q;
        const float scale = 0.17677669529663689f;

        float4 qv[8];
        {
            const float4* qp = (const float4*)(g_qkv + ((size_t)b * S + qg) * (3 * P));
#pragma unroll
            for (int i = 0; i < 8; i++) qv[i] = __ldg(qp + i);
        }
        float av0[4] = {0.f, 0.f, 0.f, 0.f}, av1[4] = {0.f, 0.f, 0.f, 0.f};
        float mrun = -1e30f, lrun = 0.f;

        for (int kt = 0; kt < 8; kt++) {
            __syncthreads();
            for (int i = tid; i < 64 * P; i += 256) {
                int row = i >> 5, d = i & 31;
                const float* base = g_qkv + ((size_t)b * S + kt * 64 + row) * (3 * P);
                Ks[row * 36 + d] = base[P + d];
                Vs[row * 36 + d] = base[2 * P + d];
            }
            __syncthreads();

            float sv[16];
            float tmax = -1e30f;
#pragma unroll
            for (int kl = 0; kl < 16; kl++) {
                int k = kg + kl * 4;
                const float4* kr = (const float4*)(Ks + k * 36);
                float d0 = 0.f, d1 = 0.f, d2 = 0.f, d3 = 0.f;
#pragma unroll
                for (int i = 0; i < 8; i += 4) {
                    float4 k0 = kr[i], k1 = kr[i + 1], k2 = kr[i + 2], k3 = kr[i + 3];
                    d0 = fmaf(qv[i].x, k0.x, d0); d0 = fmaf(qv[i].y, k0.y, d0);
                    d0 = fmaf(qv[i].z, k0.z, d0); d0 = fmaf(qv[i].w, k0.w, d0);
                    d1 = fmaf(qv[i+1].x, k1.x, d1); d1 = fmaf(qv[i+1].y, k1.y, d1);
                    d1 = fmaf(qv[i+1].z, k1.z, d1); d1 = fmaf(qv[i+1].w, k1.w, d1);
                    d2 = fmaf(qv[i+2].x, k2.x, d2); d2 = fmaf(qv[i+2].y, k2.y, d2);
                    d2 = fmaf(qv[i+2].z, k2.z, d2); d2 = fmaf(qv[i+2].w, k2.w, d2);
                    d3 = fmaf(qv[i+3].x, k3.x, d3); d3 = fmaf(qv[i+3].y, k3.y, d3);
                    d3 = fmaf(qv[i+3].z, k3.z, d3); d3 = fmaf(qv[i+3].w, k3.w, d3);
                }
                sv[kl] = ((d0 + d1) + (d2 + d3)) * scale;
                tmax = fmaxf(tmax, sv[kl]);
            }
            tmax = fmaxf(tmax, __shfl_xor_sync(0xffffffffu, tmax, 1));
            tmax = fmaxf(tmax, __shfl_xor_sync(0xffffffffu, tmax, 2));
            float mnew = fmaxf(mrun, tmax);
            float corr = __expf(mrun - mnew);
            float tsum = 0.f;
#pragma unroll
            for (int kl = 0; kl < 16; kl++) {
                float e = __expf(sv[kl] - mnew);
                psh[q * 68 + kg + kl * 4] = e;
                tsum += e;
            }
            tsum += __shfl_xor_sync(0xffffffffu, tsum, 1);
            tsum += __shfl_xor_sync(0xffffffffu, tsum, 2);
            lrun = lrun * corr + tsum;
            mrun = mnew;
#pragma unroll
            for (int j = 0; j < 4; j++) { av0[j] *= corr; av1[j] *= corr; }
            __syncwarp();
#pragma unroll 4
            for (int k = 0; k < 64; k++) {
                float pv = psh[q * 68 + k];
                const float4* vr = (const float4*)(Vs + k * 36 + kg * 8);
                float4 v0 = vr[0], v1 = vr[1];
                av0[0] = fmaf(pv, v0.x, av0[0]); av0[1] = fmaf(pv, v0.y, av0[1]);
                av0[2] = fmaf(pv, v0.z, av0[2]); av0[3] = fmaf(pv, v0.w, av0[3]);
                av1[0] = fmaf(pv, v1.x, av1[0]); av1[1] = fmaf(pv, v1.y, av1[1]);
                av1[2] = fmaf(pv, v1.z, av1[2]); av1[3] = fmaf(pv, v1.w, av1[3]);
            }
            __syncwarp();
        }
        float inv = 1.0f / lrun;
        float* op = g_av + ((size_t)b * S + qg) * P + kg * 8;
        *(float4*)(op) = make_float4(av0[0] * inv, av0[1] * inv, av0[2] * inv, av0[3] * inv);
        *(float4*)(op + 4) = make_float4(av1[0] * inv, av1[1] * inv, av1[2] * inv, av1[3] * inv);
    }
}

// =================================================================
// PREP: bert->bf16 (0..12287) + qkv (12288..24575) + Wih->bf16 (..24719)
//       + weff/flags (last block)
// =================================================================
#define CVT_BLOCKS 12288
#define QKV_BLOCKS 12288
#define WCVT_BLOCKS 144
__global__ void prep_kernel(const float* __restrict__ bert,
                            const float* __restrict__ in2, const float* __restrict__ W,
                            const float* __restrict__ bias,
                            const float* __restrict__ Wf, const float* __restrict__ Wb,
                            const float* __restrict__ Wdense, const float* __restrict__ opw,
                            const float* __restrict__ opb, const float* __restrict__ Wfuse) {
    const int bx = blockIdx.x;
    if (bx < CVT_BLOCKS) {
        int base = bx * 2048 + threadIdx.x * 8;
        float4 v0 = *(const float4*)(bert + base);
        float4 v1 = *(const float4*)(bert + base + 4);
        __nv_bfloat162 h0 = __floats2bfloat162_rn(v0.x, v0.y);
        __nv_bfloat162 h1 = __floats2bfloat162_rn(v0.z, v0.w);
        __nv_bfloat162 h2 = __floats2bfloat162_rn(v1.x, v1.y);
        __nv_bfloat162 h3 = __floats2bfloat162_rn(v1.z, v1.w);
        uint4 o;
        o.x = *(uint32_t*)&h0; o.y = *(uint32_t*)&h1;
        o.z = *(uint32_t*)&h2; o.w = *(uint32_t*)&h3;
        *(uint4*)(g_bert_h + base) = o;
    } else if (bx < CVT_BLOCKS + QKV_BLOCKS) {
        int idx = (bx - CVT_BLOCKS) * 256 + threadIdx.x;
        int m = idx / (3 * P);
        int n = idx % (3 * P);
        const float4* x = (const float4*)(in2 + (size_t)m * P);
        const float4* wv = (const float4*)(W + (size_t)n * P);
        float acc = bias[n];
#pragma unroll
        for (int k = 0; k < 8; k++) {
            float4 a = __ldg(x + k), b = __ldg(wv + k);
            acc = fmaf(a.x, b.x, acc); acc = fmaf(a.y, b.y, acc);
            acc = fmaf(a.z, b.z, acc); acc = fmaf(a.w, b.w, acc);
        }
        g_qkv[idx] = acc;
    } else if (bx < CVT_BLOCKS + QKV_BLOCKS + WCVT_BLOCKS) {
        int base = (bx - CVT_BLOCKS - QKV_BLOCKS) * 2048 + threadIdx.x * 8;
        const int half = G * E;   // 147456
        const float* src = (base < half) ? (Wf + base) : (Wb + base - half);
        float4 v0 = *(const float4*)(src);
        float4 v1 = *(const float4*)(src + 4);
        __nv_bfloat162 h0 = __floats2bfloat162_rn(v0.x, v0.y);
        __nv_bfloat162 h1 = __floats2bfloat162_rn(v0.z, v0.w);
        __nv_bfloat162 h2 = __floats2bfloat162_rn(v1.x, v1.y);
        __nv_bfloat162 h3 = __floats2bfloat162_rn(v1.z, v1.w);
        uint4 o;
        o.x = *(uint32_t*)&h0; o.y = *(uint32_t*)&h1;
        o.z = *(uint32_t*)&h2; o.w = *(uint32_t*)&h3;
        *(uint4*)(g_wh + base) = o;
    } else {
        int tid = threadIdx.x;
        for (int i = tid; i < 256 * 3; i += 256) g_flags[i] = 0;
        for (int i = tid; i < 2 * H * T; i += 256) {
            int t = i >> 7, j = i & 127;
            float s = 0.f;
#pragma unroll
            for (int u = 0; u < T; u++) s = fmaf(Wdense[j * T + u], Wfuse[u * T + t], s);
            g_weff1T[t * 2 * H + j] = s;
        }
        for (int i = tid; i < P * T; i += 256) {
            int t = i >> 5, d = i & 31;
            float s = 0.f;
#pragma unroll
            for (int p = 0; p < P; p++) s = fmaf(opw[p * P + d], Wfuse[(T + p) * T + t], s);
            g_weff2T[t * P + d] = s;
        }
        if (tid < T) {
            float s = 0.f;
#pragma unroll
            for (int p = 0; p < P; p++) s = fmaf(opb[p], Wfuse[(T + p) * T + tid], s);
            g_beff[tid] = s;
        }
        __threadfence();
    }
}

// ---------------- emissions ----------------
__global__ void __launch_bounds__(256) emis_kernel() {
    __shared__ float lrow[16 * 2 * H];
    __shared__ float arow[16 * P];
    __shared__ float w1s[T * 133];
    __shared__ float w2s[T * 37];
    __shared__ float bes[T];
    const int tid = threadIdx.x;
    const int r0 = blockIdx.x * 16;

    for (int i = tid; i < 16 * 2 * H; i += 256) lrow[i] = g_lstm[(size_t)r0 * 2 * H + i];
    for (int i = tid; i < 16 * P; i += 256) arow[i] = g_av[(size_t)r0 * P + i];
    for (int i = tid; i < T * 2 * H; i += 256) {
        int t = i >> 7, j = i & 127;
        w1s[t * 133 + j] = g_weff1T[i];
    }
    for (int i = tid; i < T * P; i += 256) {
        int t = i >> 5, d = i & 31;
        w2s[t * 37 + d] = g_weff2T[i];
    }
    if (tid < T) bes[tid] = g_beff[tid];
    __syncthreads();

    const int rr = tid >> 4;
    const int t = tid & 15;
    float acc = bes[t];
    const float* lr = lrow + rr * 2 * H;
    const float* w1 = w1s + t * 133;
#pragma unroll
    for (int i = 0; i < 2 * H; i += 4) {
        acc = fmaf(lr[i], w1[i], acc);
        acc = fmaf(lr[i + 1], w1[i + 1], acc);
        acc = fmaf(lr[i + 2], w1[i + 2], acc);
        acc = fmaf(lr[i + 3], w1[i + 3], acc);
    }
    const float* ar = arow + rr * P;
    const float* w2 = w2s + t * 37;
#pragma unroll
    for (int i = 0; i < P; i += 4) {
        acc = fmaf(ar[i], w2[i], acc);
        acc = fmaf(ar[i + 1], w2[i + 1], acc);
        acc = fmaf(ar[i + 2], w2[i + 2], acc);
        acc = fmaf(ar[i + 3], w2[i + 3], acc);
    }
    g_emis[(size_t)(r0 + rr) * T + t] = acc;
}

// =================================================================
// CRF: 64 threads/batch. Warp 0: forward alpha to t=255.
//      Warp 1: backward beta from t=511 down to 255.
//      denom = LSE(alpha_255 + beta_255).
// =================================================================
__global__ void __launch_bounds__(64) crf_kernel(
    const int* __restrict__ targets, const float* __restrict__ crf_start,
    const float* __restrict__ crf_end, const float* __restrict__ crf_trans)
{
    __shared__ float tr[T * 17];
    __shared__ float alpha_s[T];
    __shared__ float beta_s[T];
    __shared__ float numw[2];
    const int b = blockIdx.x;
    const int tid = threadIdx.x;
    const int wid = tid >> 5, lane = tid & 31;
    const int j = lane & 15, half = lane >> 4;

    for (int i = tid; i < T * T; i += 64) tr[(i >> 4) * 17 + (i & 15)] = crf_trans[i];
    __syncthreads();

    // numerator (both warps, strided 64)
    const int* tg = targets + (size_t)b * S;
    {
        float num = 0.f;
        for (int t = tid; t < S; t += 64) {
            int cur = tg[t];
            num += g_emis[((size_t)b * S + t) * T + cur];
            if (t < S - 1) num += tr[cur * 17 + tg[t + 1]];
        }
#pragma unroll
        for (int o = 16; o > 0; o >>= 1) num += __shfl_xor_sync(0xffffffffu, num, o);
        if (lane == 0) numw[wid] = num;
    }

    const float* em_b = g_emis + (size_t)b * S * T;
    const int src_base = half * 24;   // e_k holder lanes: half*24 + i

    if (wid == 0) {
        // forward: alpha_t, t = 0..255
        float Ereg[8];
#pragma unroll
        for (int k = 0; k < 8; k++) Ereg[k] = __expf(tr[(half * 8 + k) * 17 + j]);
        float a = crf_start[j] + em_b[j];
        float em = em_b[T + j];
        for (int t = 1; t <= 255; t++) {
            float em_next = em_b[(t + 1) * T + j];   // t=255 reads row 256 (valid)
            float anchor = __shfl_sync(0xffffffffu, a, 0);
            float e = __expf(a - anchor);
            float acc0 = 0.f, acc1 = 0.f;
#pragma unroll
            for (int i = 0; i < 8; i += 2) {
                float e0 = __shfl_sync(0xffffffffu, e, src_base + i);
                float e1 = __shfl_sync(0xffffffffu, e, src_base + i + 1);
                acc0 = fmaf(e0, Ereg[i], acc0);
                acc1 = fmaf(e1, Ereg[i + 1], acc1);
            }
            float acc = acc0 + acc1;
            acc += __shfl_xor_sync(0xffffffffu, acc, 16);
            a = anchor + __logf(acc) + em;
            em = em_next;
        }
        if (half == 0) alpha_s[j] = a;
    } else {
        // backward: beta_t, t = 511 down to 255
        float EregB[8];
#pragma unroll
        for (int i2 = 0; i2 < 8; i2++) EregB[i2] = __expf(tr[j * 17 + half * 8 + i2]);
        float bt = crf_end[j];
        float em1 = em_b[511 * T + j];
        for (int t = 510; t >= 255; t--) {
            float em_next = (t > 255) ? em_b[t * T + j] : 0.f;
            float g = bt + em1;
            float anchor = __shfl_sync(0xffffffffu, g, 0);
            float e = __expf(g - anchor);
            float acc0 = 0.f, acc1 = 0.f;
#pragma unroll
            for (int i2 = 0; i2 < 8; i2 += 2) {
                float e0 = __shfl_sync(0xffffffffu, e, src_base + i2);
                float e1 = __shfl_sync(0xffffffffu, e, src_base + i2 + 1);
                acc0 = fmaf(e0, EregB[i2], acc0);
                acc1 = fmaf(e1, EregB[i2 + 1], acc1);
            }
            float acc = acc0 + acc1;
            acc += __shfl_xor_sync(0xffffffffu, acc, 16);
            bt = anchor + __logf(acc);
            em1 = em_next;
        }
        if (half == 0) beta_s[j] = bt;
    }
    __syncthreads();

    if (wid == 0) {
        float v = (lane < T) ? (alpha_s[lane] + beta_s[lane]) : -1e30f;
        float m = v;
#pragma unroll
        for (int o = 16; o > 0; o >>= 1) m = fmaxf(m, __shfl_xor_sync(0xffffffffu, m, o));
        float e = (lane < T) ? __expf(v - m) : 0.f;
#pragma unroll
        for (int o = 16; o > 0; o >>= 1) e += __shfl_xor_sync(0xffffffffu, e, o);
        if (lane == 0) {
            float s_num = numw[0] + numw[1] + crf_start[tg[0]] + crf_end[tg[S - 1]];
            g_nll[b] = (m + __logf(e)) - s_num;
        }
    }
}

// ---------------- final mean ----------------
__global__ void final_kernel(float* __restrict__ out) {
    __shared__ float red[B];
    red[threadIdx.x] = g_nll[threadIdx.x];
    __syncthreads();
    for (int stp = 32; stp > 0; stp >>= 1) {
        if (threadIdx.x < stp) red[threadIdx.x] += red[threadIdx.x + stp];
        __syncthreads();
    }
    if (threadIdx.x == 0) out[0] = red[0] * (1.0f / B);
}

// ---------------- launch ----------------
extern "C" void kernel_launch(void* const* d_in, const int* in_sizes, int n_in,
                              void* d_out, int out_size) {
    const float* bert = (const float*)d_in[0];
    const float* input2 = (const float*)d_in[1];
    const int* targets = (const int*)d_in[2];
    const float* Wih_f = (const float*)d_in[3];
    const float* Whh_f = (const float*)d_in[4];
    const float* bih_f = (const float*)d_in[5];
    const float* bhh_f = (const float*)d_in[6];
    const float* Wih_b = (const float*)d_in[7];
    const float* Whh_b = (const float*)d_in[8];
    const float* bih_b = (const float*)d_in[9];
    const float* bhh_b = (const float*)d_in[10];
    const float* Wdense = (const float*)d_in[11];
    const float* in_proj_w = (const float*)d_in[12];
    const float* in_proj_b = (const float*)d_in[13];
    const float* out_proj_w = (const float*)d_in[14];
    const float* out_proj_b = (const float*)d_in[15];
    const float* Wfuse = (const float*)d_in[16];
    const float* crf_start = (const float*)d_in[17];
    const float* crf_end = (const float*)d_in[18];
    const float* crf_trans = (const float*)d_in[19];
    float* out = (float*)d_out;

    cudaFuncSetAttribute(mega_kernel, cudaFuncAttributeMaxDynamicSharedMemorySize, DSM_BYTES);

    // prep: bf16 conversions + qkv + weff + flag reset
    prep_kernel<<<CVT_BLOCKS + QKV_BLOCKS + WCVT_BLOCKS + 1, 256>>>(
        bert, input2, in_proj_w, in_proj_b, Wih_f, Wih_b,
        Wdense, out_proj_w, out_proj_b, Wfuse);
    // GRU (0..127) + GEMM (128..895) + attention (896..1407)
    mega_kernel<<<ATTN_OFF + 512, 256, DSM_BYTES>>>(bih_f, bih_b,
                                                    Whh_f, Whh_b, bhh_f, bhh_b);
    // emissions
    emis_kernel<<<(B * S) / 16, 256>>>();
    // CRF (forward/backward split)
    crf_kernel<<<B, 64>>>(targets, crf_start, crf_end, crf_trans);
    // mean
    final_kernel<<<1, B>>>(out);
}